// round 1
// baseline (speedup 1.0000x reference)
#include <cuda_runtime.h>
#include <math.h>

// Problem constants
#define BB 2
#define SS 2048
#define DD 256
#define HH 8
#define DK 32
#define DV 32
#define DFF 512
#define NLAYER 2
#define MTOT (BB*SS)          // 4096 rows
#define QKV3 (3*DD)           // 768 (= 3*H*DK since H*DK == D)

__device__ __constant__ float kMASK_VALUE = -1e-30f;

// -------------------- scratch (static device globals; no allocation) ----------
__device__ float g_x[MTOT*DD];          // current residual stream
__device__ float g_y[MTOT*DD];          // pre-layernorm temp
__device__ float g_o[MTOT*DD];          // attention output (b,s,h,v) = (row, 256)
__device__ float g_qkv[MTOT*QKV3];      // fused q|k|v per row
__device__ float g_h[MTOT*DFF];         // ffn hidden
__device__ float g_wqkv[DD*QKV3];       // repacked [d][sel*256 + h*32 + k]

// -------------------- copy input into residual stream -------------------------
__global__ void copy_kernel(const float* __restrict__ src) {
    int i = blockIdx.x * blockDim.x + threadIdx.x;
    g_x[i] = src[i];
}

// -------------------- repack Wq/Wk/Wv -> [D, 3*H*DK] --------------------------
// W* layout: [H][D][DK]; out[d][sel*256 + h*32 + k]
__global__ void repack_qkv_kernel(const float* __restrict__ Wq,
                                  const float* __restrict__ Wk,
                                  const float* __restrict__ Wv) {
    int idx = blockIdx.x * blockDim.x + threadIdx.x;      // 0 .. 3*65536-1
    if (idx >= 3 * HH * DD * DK) return;
    int sel = idx / (HH * DD * DK);
    int r   = idx % (HH * DD * DK);
    int h   = r / (DD * DK);
    int rem = r % (DD * DK);
    int d   = rem / DK;
    int k   = rem % DK;
    const float* W = (sel == 0) ? Wq : (sel == 1) ? Wk : Wv;
    g_wqkv[d * QKV3 + sel * DD + h * DK + k] = W[r];
}

// -------------------- generic tiled fp32 GEMM with epilogue -------------------
// C[M,N] = op( A[M,K] @ B[K,N] + (BIAS? bias[n]) ) + (RES? res[M,N])
template<bool BIAS, bool RELU, bool RES>
__global__ void gemm_kernel(const float* __restrict__ A,
                            const float* __restrict__ B,
                            const float* __restrict__ bias,
                            const float* __restrict__ res,
                            float* __restrict__ C,
                            int M, int N, int K) {
    const int BM = 64, BN = 64, BK = 16;
    __shared__ float As[BK][BM + 1];
    __shared__ float Bs[BK][BN + 1];

    int t  = threadIdx.x;            // 0..255
    int tx = t % 16;                 // col group
    int ty = t / 16;                 // row group
    int row0 = blockIdx.y * BM;
    int col0 = blockIdx.x * BN;

    float acc[4][4] = {};

    for (int k0 = 0; k0 < K; k0 += BK) {
        // load A tile (BM x BK), store transposed
        #pragma unroll
        for (int l = 0; l < 4; l++) {
            int idx = t + l * 256;           // 0..1023
            int i = idx / BK, j = idx % BK;
            As[j][i] = A[(size_t)(row0 + i) * K + k0 + j];
        }
        // load B tile (BK x BN)
        #pragma unroll
        for (int l = 0; l < 4; l++) {
            int idx = t + l * 256;
            int j = idx / BN, n = idx % BN;
            Bs[j][n] = B[(size_t)(k0 + j) * N + col0 + n];
        }
        __syncthreads();

        #pragma unroll
        for (int j = 0; j < BK; j++) {
            float a[4], b[4];
            #pragma unroll
            for (int u = 0; u < 4; u++) a[u] = As[j][ty * 4 + u];
            #pragma unroll
            for (int v = 0; v < 4; v++) b[v] = Bs[j][tx * 4 + v];
            #pragma unroll
            for (int u = 0; u < 4; u++)
                #pragma unroll
                for (int v = 0; v < 4; v++)
                    acc[u][v] = fmaf(a[u], b[v], acc[u][v]);
        }
        __syncthreads();
    }

    #pragma unroll
    for (int u = 0; u < 4; u++) {
        int r = row0 + ty * 4 + u;
        #pragma unroll
        for (int v = 0; v < 4; v++) {
            int c = col0 + tx * 4 + v;
            float val = acc[u][v];
            if (BIAS) val += bias[c];
            if (RELU) val = fmaxf(val, 0.0f);
            if (RES)  val += res[(size_t)r * N + c];
            C[(size_t)r * N + c] = val;
        }
    }
}

// -------------------- flash attention ----------------------------------------
// grid: (S/128, B*H), block 128. One thread per query row.
// qkv row layout: [q(h*32+k) | k | v], stride 768.
// Output o in (b,s,h,v) layout => row-major [MTOT, 256].
__global__ void attention_kernel(const float* __restrict__ mask) {
    int bh = blockIdx.y;
    int b  = bh / HH;
    int h  = bh % HH;
    int s  = blockIdx.x * 128 + threadIdx.x;

    const float* qrow = g_qkv + (size_t)(b * SS + s) * QKV3 + h * DK;
    float q[DK];
    #pragma unroll
    for (int d = 0; d < DK; d++) q[d] = qrow[d];

    float m_i = -INFINITY, l_i = 0.0f;
    float acc[DV] = {};

    __shared__ float Ks[32][DK];
    __shared__ float Vs[32][DV];
    __shared__ float Ms[32];

    for (int t0 = 0; t0 < SS; t0 += 32) {
        int t = threadIdx.x;
        #pragma unroll
        for (int l = 0; l < 8; l++) {
            int idx = t + l * 128;           // 0..1023
            int r = idx / 32, c = idx % 32;
            size_t base = (size_t)(b * SS + t0 + r) * QKV3 + h * DK;
            Ks[r][c] = g_qkv[base + DD + c];
            Vs[r][c] = g_qkv[base + 2 * DD + c];
        }
        if (t < 32) Ms[t] = mask[b * SS + t0 + t];
        __syncthreads();

        float sc[32];
        float tmax = -INFINITY;
        #pragma unroll
        for (int j = 0; j < 32; j++) {
            float dot = 0.0f;
            #pragma unroll
            for (int d = 0; d < DK; d++) dot = fmaf(q[d], Ks[j][d], dot);
            float mv = Ms[j];
            dot = mv * dot + (1.0f - mv) * kMASK_VALUE;
            sc[j] = dot;
            tmax = fmaxf(tmax, dot);
        }
        float m_new = fmaxf(m_i, tmax);
        float corr = __expf(m_i - m_new);
        l_i *= corr;
        #pragma unroll
        for (int d = 0; d < DV; d++) acc[d] *= corr;
        #pragma unroll
        for (int j = 0; j < 32; j++) {
            float p = __expf(sc[j] - m_new);
            l_i += p;
            #pragma unroll
            for (int d = 0; d < DV; d++) acc[d] = fmaf(p, Vs[j][d], acc[d]);
        }
        m_i = m_new;
        __syncthreads();
    }

    float inv = 1.0f / l_i;
    float* orow = g_o + (size_t)(b * SS + s) * DD + h * DV;
    #pragma unroll
    for (int d = 0; d < DV; d++) orow[d] = acc[d] * inv;
}

// -------------------- layernorm ----------------------------------------------
// one block (256 threads) per row of D=256
__global__ void ln_kernel(const float* __restrict__ in, float* __restrict__ out,
                          const float* __restrict__ gamma,
                          const float* __restrict__ beta, int gi) {
    int row = blockIdx.x;
    int t = threadIdx.x;
    float v = in[(size_t)row * DD + t];

    __shared__ float sred[8];

    // mean
    float s = v;
    #pragma unroll
    for (int off = 16; off > 0; off >>= 1) s += __shfl_xor_sync(0xffffffffu, s, off);
    if ((t & 31) == 0) sred[t >> 5] = s;
    __syncthreads();
    float tot = 0.0f;
    #pragma unroll
    for (int i = 0; i < 8; i++) tot += sred[i];
    float mean = tot * (1.0f / DD);
    __syncthreads();

    // variance
    float d0 = v - mean;
    float s2 = d0 * d0;
    #pragma unroll
    for (int off = 16; off > 0; off >>= 1) s2 += __shfl_xor_sync(0xffffffffu, s2, off);
    if ((t & 31) == 0) sred[t >> 5] = s2;
    __syncthreads();
    float tot2 = 0.0f;
    #pragma unroll
    for (int i = 0; i < 8; i++) tot2 += sred[i];
    float var = tot2 * (1.0f / DD);

    float g = gamma[gi], bb = beta[gi];
    out[(size_t)row * DD + t] = d0 * rsqrtf(var + 1e-14f) * g + bb;
}

// -------------------- launch -------------------------------------------------
extern "C" void kernel_launch(void* const* d_in, const int* in_sizes, int n_in,
                              void* d_out, int out_size) {
    const float* x     = (const float*)d_in[0];
    const float* mask  = (const float*)d_in[1];
    const float* Wq    = (const float*)d_in[2];
    const float* Wk    = (const float*)d_in[3];
    const float* Wv    = (const float*)d_in[4];
    const float* Wo    = (const float*)d_in[5];
    const float* W1    = (const float*)d_in[6];
    const float* b1    = (const float*)d_in[7];
    const float* W2    = (const float*)d_in[8];
    const float* b2    = (const float*)d_in[9];
    const float* gamma = (const float*)d_in[10];
    const float* beta  = (const float*)d_in[11];
    float* out = (float*)d_out;
    (void)in_sizes; (void)n_in; (void)out_size;

    // scratch pointers
    float *p_x, *p_y, *p_o, *p_qkv, *p_h, *p_wqkv;
    cudaGetSymbolAddress((void**)&p_x,    g_x);
    cudaGetSymbolAddress((void**)&p_y,    g_y);
    cudaGetSymbolAddress((void**)&p_o,    g_o);
    cudaGetSymbolAddress((void**)&p_qkv,  g_qkv);
    cudaGetSymbolAddress((void**)&p_h,    g_h);
    cudaGetSymbolAddress((void**)&p_wqkv, g_wqkv);

    copy_kernel<<<MTOT, DD>>>(x);

    for (int i = 0; i < NLAYER; i++) {
        // 1. repack qkv weights for this layer
        repack_qkv_kernel<<<(3 * HH * DD * DK + 255) / 256, 256>>>(
            Wq + (size_t)i * HH * DD * DK,
            Wk + (size_t)i * HH * DD * DK,
            Wv + (size_t)i * HH * DD * DV);

        // 2. qkv = x @ Wqkv  (4096 x 768 x 256)
        gemm_kernel<false,false,false><<<dim3(QKV3/64, MTOT/64), 256>>>(
            p_x, p_wqkv, nullptr, nullptr, p_qkv, MTOT, QKV3, DD);

        // 3. flash attention -> o (b,s,h,v)
        attention_kernel<<<dim3(SS/128, BB*HH), 128>>>(mask);

        // 4. y = x + o @ Wo   (4096 x 256 x 256)
        gemm_kernel<false,false,true><<<dim3(DD/64, MTOT/64), 256>>>(
            p_o, Wo + (size_t)i * HH * DV * DD, nullptr, p_x, p_y, MTOT, DD, DD);

        // 5. x = LN(y, gamma[2i], beta[2i])
        ln_kernel<<<MTOT, DD>>>(p_y, p_x, gamma, beta, 2 * i);

        // 6. h = relu(x @ W1 + b1)   (4096 x 512 x 256)
        gemm_kernel<true,true,false><<<dim3(DFF/64, MTOT/64), 256>>>(
            p_x, W1 + (size_t)i * DD * DFF, b1 + (size_t)i * DFF, nullptr, p_h,
            MTOT, DFF, DD);

        // 7. y = x + h @ W2 + b2     (4096 x 256 x 512)
        gemm_kernel<true,false,true><<<dim3(DD/64, MTOT/64), 256>>>(
            p_h, W2 + (size_t)i * DFF * DD, b2 + (size_t)i * DD, p_x, p_y,
            MTOT, DD, DFF);

        // 8. LN -> x (or final output)
        float* ln_out = (i == NLAYER - 1) ? out : p_x;
        ln_kernel<<<MTOT, DD>>>(p_y, ln_out, gamma, beta, 2 * i + 1);
    }
}

// round 3
// speedup vs baseline: 1.0958x; 1.0958x over previous
#include <cuda_runtime.h>
#include <cuda_bf16.h>
#include <cstdint>
#include <math.h>

// Problem constants
#define BB 2
#define SS 2048
#define DD 256
#define HH 8
#define DK 32
#define DV 32
#define DFF 512
#define NLAYER 2
#define MTOT (BB*SS)          // 4096 rows
#define QKV3 (3*DD)           // 768

// ---------------------------------------------------------------------------
// helpers
// ---------------------------------------------------------------------------
__device__ __forceinline__ uint32_t smem_u32(const void* p) {
    uint32_t a;
    asm("{ .reg .u64 tmp; cvta.to.shared.u64 tmp, %1; cvt.u32.u64 %0, tmp; }"
        : "=r"(a) : "l"(p));
    return a;
}

__device__ __forceinline__ void ldmatrix_x4(uint32_t& a0, uint32_t& a1,
                                            uint32_t& a2, uint32_t& a3,
                                            uint32_t addr) {
    asm volatile("ldmatrix.sync.aligned.m8n8.x4.shared.b16 {%0,%1,%2,%3}, [%4];"
                 : "=r"(a0), "=r"(a1), "=r"(a2), "=r"(a3) : "r"(addr));
}

__device__ __forceinline__ void ldmatrix_x2(uint32_t& b0, uint32_t& b1,
                                            uint32_t addr) {
    asm volatile("ldmatrix.sync.aligned.m8n8.x2.shared.b16 {%0,%1}, [%2];"
                 : "=r"(b0), "=r"(b1) : "r"(addr));
}

__device__ __forceinline__ void mma_16816(float* c, uint32_t a0, uint32_t a1,
                                          uint32_t a2, uint32_t a3,
                                          uint32_t b0, uint32_t b1) {
    asm volatile(
        "mma.sync.aligned.m16n8k16.row.col.f32.bf16.bf16.f32 "
        "{%0,%1,%2,%3}, {%4,%5,%6,%7}, {%8,%9}, {%0,%1,%2,%3};"
        : "+f"(c[0]), "+f"(c[1]), "+f"(c[2]), "+f"(c[3])
        : "r"(a0), "r"(a1), "r"(a2), "r"(a3), "r"(b0), "r"(b1));
}

// ---------------------------------------------------------------------------
// Scratch (static device globals; no allocation)
// ---------------------------------------------------------------------------
__device__ float g_x[MTOT*DD];
__device__ float g_y[MTOT*DD];
__device__ float g_qkv[MTOT*QKV3];
__device__ __nv_bfloat16 g_xhi[MTOT*DD], g_xlo[MTOT*DD];
__device__ __nv_bfloat16 g_ohi[MTOT*DD], g_olo[MTOT*DD];
__device__ __nv_bfloat16 g_hhi[MTOT*DFF], g_hlo[MTOT*DFF];
__device__ __nv_bfloat16 g_wqkvhi[QKV3*DD], g_wqkvlo[QKV3*DD];
__device__ __nv_bfloat16 g_wohi[DD*DD],   g_wolo[DD*DD];
__device__ __nv_bfloat16 g_w1hi[DFF*DD],  g_w1lo[DFF*DD];
__device__ __nv_bfloat16 g_w2hi[DD*DFF],  g_w2lo[DD*DFF];

__device__ __forceinline__ void split_store(float v, __nv_bfloat16* hi,
                                            __nv_bfloat16* lo, size_t idx) {
    __nv_bfloat16 h = __float2bfloat16_rn(v);
    hi[idx] = h;
    lo[idx] = __float2bfloat16_rn(v - __bfloat162float(h));
}

// ---------------------------------------------------------------------------
// Input copy + split
// ---------------------------------------------------------------------------
__global__ void copy_kernel(const float* __restrict__ src) {
    size_t i = (size_t)blockIdx.x * blockDim.x + threadIdx.x;
    float v = src[i];
    g_x[i] = v;
    split_store(v, g_xhi, g_xlo, i);
}

// ---------------------------------------------------------------------------
// Weight packing (bf16 hi/lo, B-operand layout [N][K], K contiguous)
// ---------------------------------------------------------------------------
// QKV: out[n][d] = Wsel[h][d][k], n = sel*256 + h*32 + k
__global__ void pack_qkv_kernel(const float* __restrict__ Wq,
                                const float* __restrict__ Wk,
                                const float* __restrict__ Wv) {
    int idx = blockIdx.x * 256 + threadIdx.x;   // n*256 + d
    int n = idx >> 8, d = idx & 255;
    int sel = n >> 8;
    int r = n & 255;
    int h = r >> 5, kk = r & 31;
    const float* W = (sel == 0) ? Wq : (sel == 1) ? Wk : Wv;
    float v = W[(h * DD + d) * DK + kk];
    split_store(v, g_wqkvhi, g_wqkvlo, idx);
}

// transpose pack: in [KK][NN] row-major -> out[n*KK + k]
__global__ void pack_wt_kernel(const float* __restrict__ W,
                               __nv_bfloat16* __restrict__ hi,
                               __nv_bfloat16* __restrict__ lo,
                               int KK, int NN) {
    int idx = blockIdx.x * 256 + threadIdx.x;
    if (idx >= KK * NN) return;
    int n = idx / KK, k = idx % KK;
    float v = W[(size_t)k * NN + n];
    split_store(v, hi, lo, idx);
}

// ---------------------------------------------------------------------------
// HMMA bf16-split GEMM: C[M,N] = (Ahi+Alo)(Bhi+Blo)^T  (3 mma passes, shared
// register accumulators). CTA tile 128x64, BK=32, 8 warps (4 along M, 2 along N),
// warp tile 32x32 = 2 m-frags x 4 n-frags of m16n8k16.
// A: [M][K] bf16 row-major; B: [N][K] bf16 row-major (k contiguous).
// ---------------------------------------------------------------------------
#define ASTR 40   // smem row stride in bf16 (32 + 8 pad; 80B, 16B-aligned)

template<bool BIAS, bool RELU, bool RES, bool SPLIT, bool F32OUT>
__global__ void __launch_bounds__(256)
hmma_gemm(const __nv_bfloat16* __restrict__ Ahi, const __nv_bfloat16* __restrict__ Alo,
          const __nv_bfloat16* __restrict__ Bhi, const __nv_bfloat16* __restrict__ Blo,
          const float* __restrict__ bias, const float* __restrict__ resp,
          float* __restrict__ C, __nv_bfloat16* __restrict__ Chi,
          __nv_bfloat16* __restrict__ Clo, int M, int N, int K) {
    __shared__ __nv_bfloat16 sAhi[128 * ASTR], sAlo[128 * ASTR];
    __shared__ __nv_bfloat16 sBhi[64 * ASTR],  sBlo[64 * ASTR];

    int t = threadIdx.x, wid = t >> 5, lane = t & 31;
    int warp_m = wid & 3;        // 0..3 (32 rows each)
    int warp_n = wid >> 2;       // 0..1 (32 cols each)
    int row0 = blockIdx.y * 128, col0 = blockIdx.x * 64;

    float acc[2][4][4];
    #pragma unroll
    for (int mt = 0; mt < 2; mt++)
        #pragma unroll
        for (int nt = 0; nt < 4; nt++)
            #pragma unroll
            for (int e = 0; e < 4; e++) acc[mt][nt][e] = 0.0f;

    uint32_t aA[2] = { smem_u32(sAhi), smem_u32(sAlo) };
    uint32_t aB[2] = { smem_u32(sBhi), smem_u32(sBlo) };

    // per-lane ldmatrix offsets (in bf16 elements)
    int a_off = (warp_m * 32 + (lane & 15)) * ASTR + (lane >> 4) * 8;
    int b_off = (warp_n * 32 + (lane & 7))  * ASTR + ((lane >> 3) & 1) * 8;

    for (int kc = 0; kc < K; kc += 32) {
        // load A tiles: 128 rows x 32 bf16 = 512 uint4; 2 per thread
        #pragma unroll
        for (int l = 0; l < 2; l++) {
            int idx = t + l * 256;
            int r = idx >> 2, c4 = idx & 3;
            const size_t gsrc = (size_t)(row0 + r) * K + kc + c4 * 8;
            *(uint4*)&sAhi[r * ASTR + c4 * 8] = *(const uint4*)&Ahi[gsrc];
            *(uint4*)&sAlo[r * ASTR + c4 * 8] = *(const uint4*)&Alo[gsrc];
        }
        // load B tiles: 64 rows x 32 bf16 = 256 uint4; 1 per thread
        {
            int r = t >> 2, c4 = t & 3;
            const size_t gsrc = (size_t)(col0 + r) * K + kc + c4 * 8;
            *(uint4*)&sBhi[r * ASTR + c4 * 8] = *(const uint4*)&Bhi[gsrc];
            *(uint4*)&sBlo[r * ASTR + c4 * 8] = *(const uint4*)&Blo[gsrc];
        }
        __syncthreads();

        // 3 split passes: (hi,hi), (hi,lo), (lo,hi)
        #pragma unroll
        for (int s = 0; s < 3; s++) {
            uint32_t baseA = aA[(s == 2) ? 1 : 0];
            uint32_t baseB = aB[(s == 1) ? 1 : 0];
            #pragma unroll
            for (int kk = 0; kk < 32; kk += 16) {
                uint32_t afr[2][4];
                #pragma unroll
                for (int mt = 0; mt < 2; mt++)
                    ldmatrix_x4(afr[mt][0], afr[mt][1], afr[mt][2], afr[mt][3],
                                baseA + (uint32_t)(a_off + mt * 16 * ASTR + kk) * 2);
                uint32_t bfr[4][2];
                #pragma unroll
                for (int nt = 0; nt < 4; nt++)
                    ldmatrix_x2(bfr[nt][0], bfr[nt][1],
                                baseB + (uint32_t)(b_off + nt * 8 * ASTR + kk) * 2);
                #pragma unroll
                for (int mt = 0; mt < 2; mt++)
                    #pragma unroll
                    for (int nt = 0; nt < 4; nt++)
                        mma_16816(acc[mt][nt], afr[mt][0], afr[mt][1], afr[mt][2],
                                  afr[mt][3], bfr[nt][0], bfr[nt][1]);
            }
        }
        __syncthreads();
    }

    // epilogue: fragment layout c0,c1 at (r, c..c+1); c2,c3 at (r+8, c..c+1)
    #pragma unroll
    for (int mt = 0; mt < 2; mt++) {
        int r_lo = row0 + warp_m * 32 + mt * 16 + (lane >> 2);
        #pragma unroll
        for (int nt = 0; nt < 4; nt++) {
            int c = col0 + warp_n * 32 + nt * 8 + (lane & 3) * 2;
            #pragma unroll
            for (int half = 0; half < 2; half++) {
                int r = r_lo + half * 8;
                size_t rb = (size_t)r * N;
                #pragma unroll
                for (int e = 0; e < 2; e++) {
                    float v = acc[mt][nt][half * 2 + e];
                    int col = c + e;
                    if (BIAS) v += bias[col];
                    if (RELU) v = fmaxf(v, 0.0f);
                    if (RES)  v += resp[rb + col];
                    if (F32OUT) C[rb + col] = v;
                    if (SPLIT)  split_store(v, Chi, Clo, rb + col);
                }
            }
        }
    }
}

// ---------------------------------------------------------------------------
// Flash attention (fp32 SIMT, float4-vectorized). 128 threads = 128 query rows.
// qkv row layout: [q(h*32+k) | k | v], stride 768 floats.
// Writes o split to bf16 hi/lo (input operand of the Wo GEMM).
// ---------------------------------------------------------------------------
__global__ void __launch_bounds__(128) attention_kernel(const float* __restrict__ mask) {
    int bh = blockIdx.y;
    int b = bh >> 3, h = bh & 7;
    int s = blockIdx.x * 128 + threadIdx.x;

    const float4* qp = (const float4*)(g_qkv + (size_t)(b * SS + s) * QKV3 + h * DK);
    float4 q4[8];
    #pragma unroll
    for (int i = 0; i < 8; i++) q4[i] = qp[i];

    float m_i = -INFINITY, l_i = 0.0f;
    float4 a4[8];
    #pragma unroll
    for (int i = 0; i < 8; i++) a4[i] = make_float4(0.f, 0.f, 0.f, 0.f);

    __shared__ float4 K4[32][8];
    __shared__ float4 V4[32][8];
    __shared__ float Ms[32];

    for (int t0 = 0; t0 < SS; t0 += 32) {
        int t = threadIdx.x;
        #pragma unroll
        for (int l = 0; l < 2; l++) {
            int idx = t + l * 128;
            int r = idx >> 3, c = idx & 7;
            const float4* src = (const float4*)(g_qkv + (size_t)(b * SS + t0 + r) * QKV3 + h * DK);
            K4[r][c] = src[64 + c];    // +DD floats
            V4[r][c] = src[128 + c];   // +2*DD floats
        }
        if (t < 32) Ms[t] = mask[b * SS + t0 + t];
        __syncthreads();

        float sc[32];
        float tmax = -INFINITY;
        #pragma unroll 8
        for (int j = 0; j < 32; j++) {
            float d0 = 0.f, d1 = 0.f, d2 = 0.f, d3 = 0.f;
            #pragma unroll
            for (int i = 0; i < 8; i++) {
                float4 kk = K4[j][i];
                d0 = fmaf(q4[i].x, kk.x, d0);
                d1 = fmaf(q4[i].y, kk.y, d1);
                d2 = fmaf(q4[i].z, kk.z, d2);
                d3 = fmaf(q4[i].w, kk.w, d3);
            }
            float dot = (d0 + d1) + (d2 + d3);
            float mv = Ms[j];
            dot = mv * dot + (1.0f - mv) * (-1e-30f);
            sc[j] = dot;
            tmax = fmaxf(tmax, dot);
        }
        float m_new = fmaxf(m_i, tmax);
        float corr = __expf(m_i - m_new);
        l_i *= corr;
        #pragma unroll
        for (int i = 0; i < 8; i++) {
            a4[i].x *= corr; a4[i].y *= corr; a4[i].z *= corr; a4[i].w *= corr;
        }
        #pragma unroll 8
        for (int j = 0; j < 32; j++) {
            float p = __expf(sc[j] - m_new);
            l_i += p;
            #pragma unroll
            for (int i = 0; i < 8; i++) {
                float4 vv = V4[j][i];
                a4[i].x = fmaf(p, vv.x, a4[i].x);
                a4[i].y = fmaf(p, vv.y, a4[i].y);
                a4[i].z = fmaf(p, vv.z, a4[i].z);
                a4[i].w = fmaf(p, vv.w, a4[i].w);
            }
        }
        m_i = m_new;
        __syncthreads();
    }

    float inv = 1.0f / l_i;
    size_t ob = (size_t)(b * SS + s) * DD + h * DV;
    #pragma unroll
    for (int i = 0; i < 8; i++) {
        split_store(a4[i].x * inv, g_ohi, g_olo, ob + i * 4 + 0);
        split_store(a4[i].y * inv, g_ohi, g_olo, ob + i * 4 + 1);
        split_store(a4[i].z * inv, g_ohi, g_olo, ob + i * 4 + 2);
        split_store(a4[i].w * inv, g_ohi, g_olo, ob + i * 4 + 3);
    }
}

// ---------------------------------------------------------------------------
// LayerNorm (+ optional bf16 hi/lo split output)
// ---------------------------------------------------------------------------
__global__ void ln_kernel(const float* __restrict__ in, float* __restrict__ out,
                          __nv_bfloat16* __restrict__ hi, __nv_bfloat16* __restrict__ lo,
                          const float* __restrict__ gamma,
                          const float* __restrict__ beta, int gi) {
    int row = blockIdx.x;
    int t = threadIdx.x;
    float v = in[(size_t)row * DD + t];

    __shared__ float sred[8];

    float sum = v;
    #pragma unroll
    for (int off = 16; off > 0; off >>= 1) sum += __shfl_xor_sync(0xffffffffu, sum, off);
    if ((t & 31) == 0) sred[t >> 5] = sum;
    __syncthreads();
    float tot = 0.0f;
    #pragma unroll
    for (int i = 0; i < 8; i++) tot += sred[i];
    float mean = tot * (1.0f / DD);
    __syncthreads();

    float d0 = v - mean;
    float s2 = d0 * d0;
    #pragma unroll
    for (int off = 16; off > 0; off >>= 1) s2 += __shfl_xor_sync(0xffffffffu, s2, off);
    if ((t & 31) == 0) sred[t >> 5] = s2;
    __syncthreads();
    float tot2 = 0.0f;
    #pragma unroll
    for (int i = 0; i < 8; i++) tot2 += sred[i];
    float var = tot2 * (1.0f / DD);

    float g = gamma[gi], bb = beta[gi];
    float r = d0 * rsqrtf(var + 1e-14f) * g + bb;
    size_t idx = (size_t)row * DD + t;
    out[idx] = r;
    if (hi) split_store(r, hi, lo, idx);
}

// ---------------------------------------------------------------------------
// launch
// ---------------------------------------------------------------------------
extern "C" void kernel_launch(void* const* d_in, const int* in_sizes, int n_in,
                              void* d_out, int out_size) {
    const float* x     = (const float*)d_in[0];
    const float* mask  = (const float*)d_in[1];
    const float* Wq    = (const float*)d_in[2];
    const float* Wk    = (const float*)d_in[3];
    const float* Wv    = (const float*)d_in[4];
    const float* Wo    = (const float*)d_in[5];
    const float* W1    = (const float*)d_in[6];
    const float* b1    = (const float*)d_in[7];
    const float* W2    = (const float*)d_in[8];
    const float* b2    = (const float*)d_in[9];
    const float* gamma = (const float*)d_in[10];
    const float* beta  = (const float*)d_in[11];
    float* out = (float*)d_out;
    (void)in_sizes; (void)n_in; (void)out_size;

    float *p_x, *p_y, *p_qkv;
    __nv_bfloat16 *p_xhi, *p_xlo, *p_ohi, *p_olo, *p_hhi, *p_hlo;
    __nv_bfloat16 *p_wqkvhi, *p_wqkvlo, *p_wohi, *p_wolo, *p_w1hi, *p_w1lo, *p_w2hi, *p_w2lo;
    cudaGetSymbolAddress((void**)&p_x, g_x);
    cudaGetSymbolAddress((void**)&p_y, g_y);
    cudaGetSymbolAddress((void**)&p_qkv, g_qkv);
    cudaGetSymbolAddress((void**)&p_xhi, g_xhi);
    cudaGetSymbolAddress((void**)&p_xlo, g_xlo);
    cudaGetSymbolAddress((void**)&p_ohi, g_ohi);
    cudaGetSymbolAddress((void**)&p_olo, g_olo);
    cudaGetSymbolAddress((void**)&p_hhi, g_hhi);
    cudaGetSymbolAddress((void**)&p_hlo, g_hlo);
    cudaGetSymbolAddress((void**)&p_wqkvhi, g_wqkvhi);
    cudaGetSymbolAddress((void**)&p_wqkvlo, g_wqkvlo);
    cudaGetSymbolAddress((void**)&p_wohi, g_wohi);
    cudaGetSymbolAddress((void**)&p_wolo, g_wolo);
    cudaGetSymbolAddress((void**)&p_w1hi, g_w1hi);
    cudaGetSymbolAddress((void**)&p_w1lo, g_w1lo);
    cudaGetSymbolAddress((void**)&p_w2hi, g_w2hi);
    cudaGetSymbolAddress((void**)&p_w2lo, g_w2lo);

    copy_kernel<<<MTOT, DD>>>(x);

    for (int i = 0; i < NLAYER; i++) {
        // pack weights
        pack_qkv_kernel<<<QKV3 * DD / 256, 256>>>(
            Wq + (size_t)i * HH * DD * DK,
            Wk + (size_t)i * HH * DD * DK,
            Wv + (size_t)i * HH * DD * DV);
        pack_wt_kernel<<<DD * DD / 256, 256>>>(
            Wo + (size_t)i * HH * DV * DD, p_wohi, p_wolo, DD, DD);
        pack_wt_kernel<<<DD * DFF / 256, 256>>>(
            W1 + (size_t)i * DD * DFF, p_w1hi, p_w1lo, DD, DFF);
        pack_wt_kernel<<<DFF * DD / 256, 256>>>(
            W2 + (size_t)i * DFF * DD, p_w2hi, p_w2lo, DFF, DD);

        // qkv = x @ Wqkv      (4096 x 768 x 256) -> fp32
        hmma_gemm<false,false,false,false,true><<<dim3(QKV3/64, MTOT/128), 256>>>(
            p_xhi, p_xlo, p_wqkvhi, p_wqkvlo, nullptr, nullptr,
            p_qkv, nullptr, nullptr, MTOT, QKV3, DD);

        // flash attention -> o (bf16 split)
        attention_kernel<<<dim3(SS/128, BB*HH), 128>>>(mask);

        // y = x + o @ Wo      (4096 x 256 x 256)
        hmma_gemm<false,false,true,false,true><<<dim3(DD/64, MTOT/128), 256>>>(
            p_ohi, p_olo, p_wohi, p_wolo, nullptr, p_x,
            p_y, nullptr, nullptr, MTOT, DD, DD);

        // x = LN(y)   (+ split for W1 input)
        ln_kernel<<<MTOT, DD>>>(p_y, p_x, p_xhi, p_xlo, gamma, beta, 2*i);

        // h = relu(x @ W1 + b1)   (4096 x 512 x 256) -> bf16 split only
        hmma_gemm<true,true,false,true,false><<<dim3(DFF/64, MTOT/128), 256>>>(
            p_xhi, p_xlo, p_w1hi, p_w1lo, b1 + (size_t)i * DFF, nullptr,
            nullptr, p_hhi, p_hlo, MTOT, DFF, DD);

        // y = x + h @ W2 + b2     (4096 x 256 x 512)
        hmma_gemm<true,false,true,false,true><<<dim3(DD/64, MTOT/128), 256>>>(
            p_hhi, p_hlo, p_w2hi, p_w2lo, b2 + (size_t)i * DD, p_x,
            p_y, nullptr, nullptr, MTOT, DD, DFF);

        // LN -> x (+ split) or final out
        if (i == NLAYER - 1) {
            ln_kernel<<<MTOT, DD>>>(p_y, out, nullptr, nullptr, gamma, beta, 2*i+1);
        } else {
            ln_kernel<<<MTOT, DD>>>(p_y, p_x, p_xhi, p_xlo, gamma, beta, 2*i+1);
        }
    }
}

// round 4
// speedup vs baseline: 2.5860x; 2.3600x over previous
#include <cuda_runtime.h>
#include <cuda_bf16.h>
#include <cstdint>
#include <math.h>

// Problem constants
#define BB 2
#define SS 2048
#define DD 256
#define HH 8
#define DK 32
#define DV 32
#define DFF 512
#define NLAYER 2
#define MTOT (BB*SS)          // 4096 rows
#define QKV3 (3*DD)           // 768

#define LOG2E 1.4426950408889634f
#define MV2L (-1e-30f * LOG2E)

// ---------------------------------------------------------------------------
// helpers
// ---------------------------------------------------------------------------
__device__ __forceinline__ uint32_t smem_u32(const void* p) {
    uint32_t a;
    asm("{ .reg .u64 tmp; cvta.to.shared.u64 tmp, %1; cvt.u32.u64 %0, tmp; }"
        : "=r"(a) : "l"(p));
    return a;
}

__device__ __forceinline__ void ldmatrix_x4(uint32_t& a0, uint32_t& a1,
                                            uint32_t& a2, uint32_t& a3,
                                            uint32_t addr) {
    asm volatile("ldmatrix.sync.aligned.m8n8.x4.shared.b16 {%0,%1,%2,%3}, [%4];"
                 : "=r"(a0), "=r"(a1), "=r"(a2), "=r"(a3) : "r"(addr));
}

__device__ __forceinline__ void ldmatrix_x2(uint32_t& b0, uint32_t& b1,
                                            uint32_t addr) {
    asm volatile("ldmatrix.sync.aligned.m8n8.x2.shared.b16 {%0,%1}, [%2];"
                 : "=r"(b0), "=r"(b1) : "r"(addr));
}

__device__ __forceinline__ void ldmatrix_x2_trans(uint32_t& b0, uint32_t& b1,
                                                  uint32_t addr) {
    asm volatile("ldmatrix.sync.aligned.m8n8.x2.trans.shared.b16 {%0,%1}, [%2];"
                 : "=r"(b0), "=r"(b1) : "r"(addr));
}

__device__ __forceinline__ void mma_16816(float* c, uint32_t a0, uint32_t a1,
                                          uint32_t a2, uint32_t a3,
                                          uint32_t b0, uint32_t b1) {
    asm volatile(
        "mma.sync.aligned.m16n8k16.row.col.f32.bf16.bf16.f32 "
        "{%0,%1,%2,%3}, {%4,%5,%6,%7}, {%8,%9}, {%0,%1,%2,%3};"
        : "+f"(c[0]), "+f"(c[1]), "+f"(c[2]), "+f"(c[3])
        : "r"(a0), "r"(a1), "r"(a2), "r"(a3), "r"(b0), "r"(b1));
}

__device__ __forceinline__ float ex2f(float x) {
    float r;
    asm("ex2.approx.f32 %0, %1;" : "=f"(r) : "f"(x));
    return r;
}

__device__ __forceinline__ uint32_t pack_bf16x2(float lo, float hi) {
    __nv_bfloat162 v = __floats2bfloat162_rn(lo, hi);   // x=lo(low half), y=hi
    return *(uint32_t*)&v;
}

// ---------------------------------------------------------------------------
// Scratch (static device globals; no allocation)
// ---------------------------------------------------------------------------
__device__ float g_x[MTOT*DD];
__device__ float g_y[MTOT*DD];
__device__ __nv_bfloat16 g_xhi[MTOT*DD], g_xlo[MTOT*DD];
__device__ __nv_bfloat16 g_qkvhi[MTOT*QKV3], g_qkvlo[MTOT*QKV3];
__device__ __nv_bfloat16 g_ohi[MTOT*DD], g_olo[MTOT*DD];
__device__ __nv_bfloat16 g_hhi[MTOT*DFF], g_hlo[MTOT*DFF];
__device__ __nv_bfloat16 g_wqkvhi[QKV3*DD], g_wqkvlo[QKV3*DD];
__device__ __nv_bfloat16 g_wohi[DD*DD],   g_wolo[DD*DD];
__device__ __nv_bfloat16 g_w1hi[DFF*DD],  g_w1lo[DFF*DD];
__device__ __nv_bfloat16 g_w2hi[DD*DFF],  g_w2lo[DD*DFF];

__device__ __forceinline__ void split_store(float v, __nv_bfloat16* hi,
                                            __nv_bfloat16* lo, size_t idx) {
    __nv_bfloat16 h = __float2bfloat16_rn(v);
    hi[idx] = h;
    lo[idx] = __float2bfloat16_rn(v - __bfloat162float(h));
}

// ---------------------------------------------------------------------------
// Input copy + split
// ---------------------------------------------------------------------------
__global__ void copy_kernel(const float* __restrict__ src) {
    size_t i = (size_t)blockIdx.x * blockDim.x + threadIdx.x;
    float v = src[i];
    g_x[i] = v;
    split_store(v, g_xhi, g_xlo, i);
}

// ---------------------------------------------------------------------------
// Weight packing
// ---------------------------------------------------------------------------
// QKV: out[n][d] = Wsel[h][d][k], n = sel*256 + h*32 + k
__global__ void pack_qkv_kernel(const float* __restrict__ Wq,
                                const float* __restrict__ Wk,
                                const float* __restrict__ Wv) {
    int idx = blockIdx.x * 256 + threadIdx.x;   // n*256 + d
    int n = idx >> 8, d = idx & 255;
    int sel = n >> 8;
    int r = n & 255;
    int h = r >> 5, kk = r & 31;
    const float* W = (sel == 0) ? Wq : (sel == 1) ? Wk : Wv;
    float v = W[(h * DD + d) * DK + kk];
    split_store(v, g_wqkvhi, g_wqkvlo, idx);
}

// transpose pack via smem tile: in [KK][NN] row-major -> out[n*KK + k]
__global__ void pack_wt_kernel(const float* __restrict__ W,
                               __nv_bfloat16* __restrict__ hi,
                               __nv_bfloat16* __restrict__ lo,
                               int KK, int NN) {
    __shared__ float tile[32][33];
    int k0 = blockIdx.x * 32, n0 = blockIdx.y * 32;
    int tx = threadIdx.x & 31, ty = threadIdx.x >> 5;   // 32 x 8
    #pragma unroll
    for (int l = 0; l < 4; l++) {
        int k = ty + l * 8;
        tile[k][tx] = W[(size_t)(k0 + k) * NN + n0 + tx];
    }
    __syncthreads();
    #pragma unroll
    for (int l = 0; l < 4; l++) {
        int n = ty + l * 8;
        float v = tile[tx][n];
        split_store(v, hi, lo, (size_t)(n0 + n) * KK + k0 + tx);
    }
}

// ---------------------------------------------------------------------------
// HMMA bf16-split GEMM (CTA tile 128x64, BK=32, 8 warps 4x2)
// A: [M][K] bf16 row-major; B: [N][K] bf16 row-major (k contiguous).
// ---------------------------------------------------------------------------
#define ASTR 40   // smem row stride in bf16 (80B; conflict-free for ldmatrix)

template<bool BIAS, bool RELU, bool RES, bool SPLIT, bool F32OUT, bool SCALEQ>
__global__ void __launch_bounds__(256)
hmma_gemm(const __nv_bfloat16* __restrict__ Ahi, const __nv_bfloat16* __restrict__ Alo,
          const __nv_bfloat16* __restrict__ Bhi, const __nv_bfloat16* __restrict__ Blo,
          const float* __restrict__ bias, const float* __restrict__ resp,
          float* __restrict__ C, __nv_bfloat16* __restrict__ Chi,
          __nv_bfloat16* __restrict__ Clo, int M, int N, int K) {
    __shared__ __nv_bfloat16 sAhi[128 * ASTR], sAlo[128 * ASTR];
    __shared__ __nv_bfloat16 sBhi[64 * ASTR],  sBlo[64 * ASTR];

    int t = threadIdx.x, wid = t >> 5, lane = t & 31;
    int warp_m = wid & 3;
    int warp_n = wid >> 2;
    int row0 = blockIdx.y * 128, col0 = blockIdx.x * 64;

    float acc[2][4][4];
    #pragma unroll
    for (int mt = 0; mt < 2; mt++)
        #pragma unroll
        for (int nt = 0; nt < 4; nt++)
            #pragma unroll
            for (int e = 0; e < 4; e++) acc[mt][nt][e] = 0.0f;

    uint32_t aA[2] = { smem_u32(sAhi), smem_u32(sAlo) };
    uint32_t aB[2] = { smem_u32(sBhi), smem_u32(sBlo) };

    int a_off = (warp_m * 32 + (lane & 15)) * ASTR + (lane >> 4) * 8;
    int b_off = (warp_n * 32 + (lane & 7))  * ASTR + ((lane >> 3) & 1) * 8;

    for (int kc = 0; kc < K; kc += 32) {
        #pragma unroll
        for (int l = 0; l < 2; l++) {
            int idx = t + l * 256;
            int r = idx >> 2, c4 = idx & 3;
            const size_t gsrc = (size_t)(row0 + r) * K + kc + c4 * 8;
            *(uint4*)&sAhi[r * ASTR + c4 * 8] = *(const uint4*)&Ahi[gsrc];
            *(uint4*)&sAlo[r * ASTR + c4 * 8] = *(const uint4*)&Alo[gsrc];
        }
        {
            int r = t >> 2, c4 = t & 3;
            const size_t gsrc = (size_t)(col0 + r) * K + kc + c4 * 8;
            *(uint4*)&sBhi[r * ASTR + c4 * 8] = *(const uint4*)&Bhi[gsrc];
            *(uint4*)&sBlo[r * ASTR + c4 * 8] = *(const uint4*)&Blo[gsrc];
        }
        __syncthreads();

        #pragma unroll
        for (int s = 0; s < 3; s++) {
            uint32_t baseA = aA[(s == 2) ? 1 : 0];
            uint32_t baseB = aB[(s == 1) ? 1 : 0];
            #pragma unroll
            for (int kk = 0; kk < 32; kk += 16) {
                uint32_t afr[2][4];
                #pragma unroll
                for (int mt = 0; mt < 2; mt++)
                    ldmatrix_x4(afr[mt][0], afr[mt][1], afr[mt][2], afr[mt][3],
                                baseA + (uint32_t)(a_off + mt * 16 * ASTR + kk) * 2);
                uint32_t bfr[4][2];
                #pragma unroll
                for (int nt = 0; nt < 4; nt++)
                    ldmatrix_x2(bfr[nt][0], bfr[nt][1],
                                baseB + (uint32_t)(b_off + nt * 8 * ASTR + kk) * 2);
                #pragma unroll
                for (int mt = 0; mt < 2; mt++)
                    #pragma unroll
                    for (int nt = 0; nt < 4; nt++)
                        mma_16816(acc[mt][nt], afr[mt][0], afr[mt][1], afr[mt][2],
                                  afr[mt][3], bfr[nt][0], bfr[nt][1]);
            }
        }
        __syncthreads();
    }

    #pragma unroll
    for (int mt = 0; mt < 2; mt++) {
        int r_lo = row0 + warp_m * 32 + mt * 16 + (lane >> 2);
        #pragma unroll
        for (int nt = 0; nt < 4; nt++) {
            int c = col0 + warp_n * 32 + nt * 8 + (lane & 3) * 2;
            #pragma unroll
            for (int half = 0; half < 2; half++) {
                int r = r_lo + half * 8;
                size_t rb = (size_t)r * N;
                #pragma unroll
                for (int e = 0; e < 2; e++) {
                    float v = acc[mt][nt][half * 2 + e];
                    int col = c + e;
                    if (BIAS) v += bias[col];
                    if (RELU) v = fmaxf(v, 0.0f);
                    if (RES)  v += resp[rb + col];
                    if (SCALEQ) { if (col < DD) v *= LOG2E; }
                    if (F32OUT) C[rb + col] = v;
                    if (SPLIT)  split_store(v, Chi, Clo, rb + col);
                }
            }
        }
    }
}

// ---------------------------------------------------------------------------
// HMMA flash attention. 128 queries/CTA, 64-key tiles, 4 warps (32 rows each).
// q pre-scaled by log2e in QKV GEMM epilogue; exp via ex2.approx.
// QK: 3 split passes (Qhi/Qlo x Khi/Klo). PV: P bf16 x (Vhi + Vlo).
// ---------------------------------------------------------------------------
__global__ void __launch_bounds__(128) attention_hmma(const float* __restrict__ mask) {
    __shared__ __nv_bfloat16 sQ[2][128 * ASTR];
    __shared__ __nv_bfloat16 sKV[4][64 * ASTR];   // Khi, Klo, Vhi, Vlo
    __shared__ float sM[64];

    int b = blockIdx.y >> 3, h = blockIdx.y & 7;
    int t = threadIdx.x, warp = t >> 5, lane = t & 31;
    int row0 = blockIdx.x * 128;

    // load Q tile (hi/lo)
    {
        size_t qbase = (size_t)(b * SS + row0) * QKV3 + h * DK;
        #pragma unroll
        for (int l = 0; l < 8; l++) {
            int idx = t + l * 128;               // 0..1023
            int r = idx >> 3, which = (idx >> 2) & 1, c4 = idx & 3;
            const __nv_bfloat16* src = which ? g_qkvlo : g_qkvhi;
            *(uint4*)&sQ[which][r * ASTR + c4 * 8] =
                *(const uint4*)&src[qbase + (size_t)r * QKV3 + c4 * 8];
        }
    }
    __syncthreads();

    // Q fragments (persist in regs)
    uint32_t qf[2][2][2][4];   // [hi/lo][mt][kstep][4]
    {
        int a_off = (warp * 32 + (lane & 15)) * ASTR + (lane >> 4) * 8;
        #pragma unroll
        for (int w2 = 0; w2 < 2; w2++) {
            uint32_t base = smem_u32(sQ[w2]);
            #pragma unroll
            for (int mt = 0; mt < 2; mt++)
                #pragma unroll
                for (int ks = 0; ks < 2; ks++)
                    ldmatrix_x4(qf[w2][mt][ks][0], qf[w2][mt][ks][1],
                                qf[w2][mt][ks][2], qf[w2][mt][ks][3],
                                base + (uint32_t)(a_off + mt * 16 * ASTR + ks * 16) * 2);
        }
    }

    float m_run[2][2], l_run[2][2], oacc[2][4][4];
    #pragma unroll
    for (int mt = 0; mt < 2; mt++) {
        #pragma unroll
        for (int hf = 0; hf < 2; hf++) { m_run[mt][hf] = -1e30f; l_run[mt][hf] = 0.f; }
        #pragma unroll
        for (int nt = 0; nt < 4; nt++)
            #pragma unroll
            for (int e = 0; e < 4; e++) oacc[mt][nt][e] = 0.f;
    }

    for (int t0 = 0; t0 < SS; t0 += 64) {
        // load K/V hi/lo tiles + mask
        #pragma unroll
        for (int l = 0; l < 8; l++) {
            int idx = t + l * 128;               // 0..1023
            int r = idx >> 4, which = (idx >> 2) & 3, c4 = idx & 3;
            const __nv_bfloat16* src = (which & 1) ? g_qkvlo : g_qkvhi;
            int coff = ((which < 2) ? DD : 2 * DD) + h * DK + c4 * 8;
            *(uint4*)&sKV[which][r * ASTR + c4 * 8] =
                *(const uint4*)&src[(size_t)(b * SS + t0 + r) * QKV3 + coff];
        }
        if (t < 64) sM[t] = mask[b * SS + t0 + t];
        __syncthreads();

        // S = (scaled Q) K^T, 3 split passes
        float sc[2][8][4];
        #pragma unroll
        for (int mt = 0; mt < 2; mt++)
            #pragma unroll
            for (int nt = 0; nt < 8; nt++)
                #pragma unroll
                for (int e = 0; e < 4; e++) sc[mt][nt][e] = 0.f;
        {
            int b_off = (lane & 7) * ASTR + ((lane >> 3) & 1) * 8;
            #pragma unroll
            for (int s = 0; s < 3; s++) {
                int wa = (s == 2) ? 1 : 0;
                uint32_t kbase = smem_u32(sKV[(s == 1) ? 1 : 0]);
                #pragma unroll
                for (int ks = 0; ks < 2; ks++)
                    #pragma unroll
                    for (int nt = 0; nt < 8; nt++) {
                        uint32_t b0, b1;
                        ldmatrix_x2(b0, b1,
                            kbase + (uint32_t)(b_off + nt * 8 * ASTR + ks * 16) * 2);
                        mma_16816(sc[0][nt], qf[wa][0][ks][0], qf[wa][0][ks][1],
                                  qf[wa][0][ks][2], qf[wa][0][ks][3], b0, b1);
                        mma_16816(sc[1][nt], qf[wa][1][ks][0], qf[wa][1][ks][1],
                                  qf[wa][1][ks][2], qf[wa][1][ks][3], b0, b1);
                    }
            }
        }

        // mask + tile max
        float tmax[2][2] = {{-1e30f, -1e30f}, {-1e30f, -1e30f}};
        #pragma unroll
        for (int nt = 0; nt < 8; nt++) {
            int c0 = nt * 8 + (lane & 3) * 2;
            float mvA = sM[c0], mvB = sM[c0 + 1];
            float cA = (1.f - mvA) * MV2L, cB = (1.f - mvB) * MV2L;
            #pragma unroll
            for (int mt = 0; mt < 2; mt++) {
                sc[mt][nt][0] = fmaf(mvA, sc[mt][nt][0], cA);
                sc[mt][nt][1] = fmaf(mvB, sc[mt][nt][1], cB);
                sc[mt][nt][2] = fmaf(mvA, sc[mt][nt][2], cA);
                sc[mt][nt][3] = fmaf(mvB, sc[mt][nt][3], cB);
                tmax[mt][0] = fmaxf(tmax[mt][0], fmaxf(sc[mt][nt][0], sc[mt][nt][1]));
                tmax[mt][1] = fmaxf(tmax[mt][1], fmaxf(sc[mt][nt][2], sc[mt][nt][3]));
            }
        }
        float corr[2][2];
        #pragma unroll
        for (int mt = 0; mt < 2; mt++)
            #pragma unroll
            for (int hf = 0; hf < 2; hf++) {
                float v = tmax[mt][hf];
                v = fmaxf(v, __shfl_xor_sync(0xffffffffu, v, 1));
                v = fmaxf(v, __shfl_xor_sync(0xffffffffu, v, 2));
                float mn = fmaxf(m_run[mt][hf], v);
                corr[mt][hf] = ex2f(m_run[mt][hf] - mn);
                m_run[mt][hf] = mn;
                l_run[mt][hf] *= corr[mt][hf];
            }
        #pragma unroll
        for (int mt = 0; mt < 2; mt++)
            #pragma unroll
            for (int nt = 0; nt < 4; nt++)
                #pragma unroll
                for (int e = 0; e < 4; e++)
                    oacc[mt][nt][e] *= corr[mt][e >> 1];

        // p = exp2(sc - m), pack into A-fragments
        uint32_t pf[2][4][4];
        #pragma unroll
        for (int mt = 0; mt < 2; mt++)
            #pragma unroll
            for (int nt = 0; nt < 8; nt++) {
                float p0 = ex2f(sc[mt][nt][0] - m_run[mt][0]);
                float p1 = ex2f(sc[mt][nt][1] - m_run[mt][0]);
                float p2 = ex2f(sc[mt][nt][2] - m_run[mt][1]);
                float p3 = ex2f(sc[mt][nt][3] - m_run[mt][1]);
                l_run[mt][0] += p0 + p1;
                l_run[mt][1] += p2 + p3;
                int kb = nt >> 1, hi2 = (nt & 1) * 2;
                pf[mt][kb][hi2 + 0] = pack_bf16x2(p0, p1);
                pf[mt][kb][hi2 + 1] = pack_bf16x2(p2, p3);
            }

        // O += P @ V   (Vhi pass + Vlo pass)
        #pragma unroll
        for (int s = 0; s < 2; s++) {
            uint32_t vbase = smem_u32(sKV[2 + s]);
            #pragma unroll
            for (int kb = 0; kb < 4; kb++) {
                uint32_t vrow = vbase + (uint32_t)((kb * 16 + (lane & 15)) * ASTR) * 2;
                #pragma unroll
                for (int nt = 0; nt < 4; nt++) {
                    uint32_t b0, b1;
                    ldmatrix_x2_trans(b0, b1, vrow + (uint32_t)(nt * 8) * 2);
                    mma_16816(oacc[0][nt], pf[0][kb][0], pf[0][kb][1],
                              pf[0][kb][2], pf[0][kb][3], b0, b1);
                    mma_16816(oacc[1][nt], pf[1][kb][0], pf[1][kb][1],
                              pf[1][kb][2], pf[1][kb][3], b0, b1);
                }
            }
        }
        __syncthreads();
    }

    // finalize: quad-sum l, normalize, split-store o
    #pragma unroll
    for (int mt = 0; mt < 2; mt++)
        #pragma unroll
        for (int hf = 0; hf < 2; hf++) {
            float v = l_run[mt][hf];
            v += __shfl_xor_sync(0xffffffffu, v, 1);
            v += __shfl_xor_sync(0xffffffffu, v, 2);
            l_run[mt][hf] = 1.0f / v;
        }
    #pragma unroll
    for (int mt = 0; mt < 2; mt++)
        #pragma unroll
        for (int hf = 0; hf < 2; hf++) {
            int row = row0 + warp * 32 + mt * 16 + (lane >> 2) + hf * 8;
            size_t obase = (size_t)(b * SS + row) * DD + h * DV;
            float inv = l_run[mt][hf];
            #pragma unroll
            for (int nt = 0; nt < 4; nt++) {
                int col = nt * 8 + (lane & 3) * 2;
                split_store(oacc[mt][nt][hf * 2 + 0] * inv, g_ohi, g_olo, obase + col);
                split_store(oacc[mt][nt][hf * 2 + 1] * inv, g_ohi, g_olo, obase + col + 1);
            }
        }
}

// ---------------------------------------------------------------------------
// LayerNorm (+ optional bf16 hi/lo split output)
// ---------------------------------------------------------------------------
__global__ void ln_kernel(const float* __restrict__ in, float* __restrict__ out,
                          __nv_bfloat16* __restrict__ hi, __nv_bfloat16* __restrict__ lo,
                          const float* __restrict__ gamma,
                          const float* __restrict__ beta, int gi) {
    int row = blockIdx.x;
    int t = threadIdx.x;
    float v = in[(size_t)row * DD + t];

    __shared__ float sred[8];

    float sum = v;
    #pragma unroll
    for (int off = 16; off > 0; off >>= 1) sum += __shfl_xor_sync(0xffffffffu, sum, off);
    if ((t & 31) == 0) sred[t >> 5] = sum;
    __syncthreads();
    float tot = 0.0f;
    #pragma unroll
    for (int i = 0; i < 8; i++) tot += sred[i];
    float mean = tot * (1.0f / DD);
    __syncthreads();

    float d0 = v - mean;
    float s2 = d0 * d0;
    #pragma unroll
    for (int off = 16; off > 0; off >>= 1) s2 += __shfl_xor_sync(0xffffffffu, s2, off);
    if ((t & 31) == 0) sred[t >> 5] = s2;
    __syncthreads();
    float tot2 = 0.0f;
    #pragma unroll
    for (int i = 0; i < 8; i++) tot2 += sred[i];
    float var = tot2 * (1.0f / DD);

    float g = gamma[gi], bb = beta[gi];
    float r = d0 * rsqrtf(var + 1e-14f) * g + bb;
    size_t idx = (size_t)row * DD + t;
    out[idx] = r;
    if (hi) split_store(r, hi, lo, idx);
}

// ---------------------------------------------------------------------------
// launch
// ---------------------------------------------------------------------------
extern "C" void kernel_launch(void* const* d_in, const int* in_sizes, int n_in,
                              void* d_out, int out_size) {
    const float* x     = (const float*)d_in[0];
    const float* mask  = (const float*)d_in[1];
    const float* Wq    = (const float*)d_in[2];
    const float* Wk    = (const float*)d_in[3];
    const float* Wv    = (const float*)d_in[4];
    const float* Wo    = (const float*)d_in[5];
    const float* W1    = (const float*)d_in[6];
    const float* b1    = (const float*)d_in[7];
    const float* W2    = (const float*)d_in[8];
    const float* b2    = (const float*)d_in[9];
    const float* gamma = (const float*)d_in[10];
    const float* beta  = (const float*)d_in[11];
    float* out = (float*)d_out;
    (void)in_sizes; (void)n_in; (void)out_size;

    float *p_x, *p_y;
    __nv_bfloat16 *p_xhi, *p_xlo, *p_qkvhi, *p_qkvlo, *p_ohi, *p_olo, *p_hhi, *p_hlo;
    __nv_bfloat16 *p_wqkvhi, *p_wqkvlo, *p_wohi, *p_wolo, *p_w1hi, *p_w1lo, *p_w2hi, *p_w2lo;
    cudaGetSymbolAddress((void**)&p_x, g_x);
    cudaGetSymbolAddress((void**)&p_y, g_y);
    cudaGetSymbolAddress((void**)&p_xhi, g_xhi);
    cudaGetSymbolAddress((void**)&p_xlo, g_xlo);
    cudaGetSymbolAddress((void**)&p_qkvhi, g_qkvhi);
    cudaGetSymbolAddress((void**)&p_qkvlo, g_qkvlo);
    cudaGetSymbolAddress((void**)&p_ohi, g_ohi);
    cudaGetSymbolAddress((void**)&p_olo, g_olo);
    cudaGetSymbolAddress((void**)&p_hhi, g_hhi);
    cudaGetSymbolAddress((void**)&p_hlo, g_hlo);
    cudaGetSymbolAddress((void**)&p_wqkvhi, g_wqkvhi);
    cudaGetSymbolAddress((void**)&p_wqkvlo, g_wqkvlo);
    cudaGetSymbolAddress((void**)&p_wohi, g_wohi);
    cudaGetSymbolAddress((void**)&p_wolo, g_wolo);
    cudaGetSymbolAddress((void**)&p_w1hi, g_w1hi);
    cudaGetSymbolAddress((void**)&p_w1lo, g_w1lo);
    cudaGetSymbolAddress((void**)&p_w2hi, g_w2hi);
    cudaGetSymbolAddress((void**)&p_w2lo, g_w2lo);

    copy_kernel<<<MTOT, DD>>>(x);

    for (int i = 0; i < NLAYER; i++) {
        pack_qkv_kernel<<<QKV3 * DD / 256, 256>>>(
            Wq + (size_t)i * HH * DD * DK,
            Wk + (size_t)i * HH * DD * DK,
            Wv + (size_t)i * HH * DD * DV);
        pack_wt_kernel<<<dim3(DD/32, DD/32), 256>>>(
            Wo + (size_t)i * HH * DV * DD, p_wohi, p_wolo, DD, DD);
        pack_wt_kernel<<<dim3(DD/32, DFF/32), 256>>>(
            W1 + (size_t)i * DD * DFF, p_w1hi, p_w1lo, DD, DFF);
        pack_wt_kernel<<<dim3(DFF/32, DD/32), 256>>>(
            W2 + (size_t)i * DFF * DD, p_w2hi, p_w2lo, DFF, DD);

        // qkv = x @ Wqkv  (split bf16 out; q columns scaled by log2e)
        hmma_gemm<false,false,false,true,false,true><<<dim3(QKV3/64, MTOT/128), 256>>>(
            p_xhi, p_xlo, p_wqkvhi, p_wqkvlo, nullptr, nullptr,
            nullptr, p_qkvhi, p_qkvlo, MTOT, QKV3, DD);

        // flash attention (tensor cores) -> o split bf16
        attention_hmma<<<dim3(SS/128, BB*HH), 128>>>(mask);

        // y = x + o @ Wo
        hmma_gemm<false,false,true,false,true,false><<<dim3(DD/64, MTOT/128), 256>>>(
            p_ohi, p_olo, p_wohi, p_wolo, nullptr, p_x,
            p_y, nullptr, nullptr, MTOT, DD, DD);

        ln_kernel<<<MTOT, DD>>>(p_y, p_x, p_xhi, p_xlo, gamma, beta, 2*i);

        // h = relu(x @ W1 + b1) -> split bf16
        hmma_gemm<true,true,false,true,false,false><<<dim3(DFF/64, MTOT/128), 256>>>(
            p_xhi, p_xlo, p_w1hi, p_w1lo, b1 + (size_t)i * DFF, nullptr,
            nullptr, p_hhi, p_hlo, MTOT, DFF, DD);

        // y = x + h @ W2 + b2
        hmma_gemm<true,false,true,false,true,false><<<dim3(DD/64, MTOT/128), 256>>>(
            p_hhi, p_hlo, p_w2hi, p_w2lo, b2 + (size_t)i * DD, p_x,
            p_y, nullptr, nullptr, MTOT, DD, DFF);

        if (i == NLAYER - 1) {
            ln_kernel<<<MTOT, DD>>>(p_y, out, nullptr, nullptr, gamma, beta, 2*i+1);
        } else {
            ln_kernel<<<MTOT, DD>>>(p_y, p_x, p_xhi, p_xlo, gamma, beta, 2*i+1);
        }
    }
}

// round 5
// speedup vs baseline: 2.6375x; 1.0199x over previous
#include <cuda_runtime.h>
#include <cuda_fp16.h>
#include <cstdint>
#include <math.h>

// Problem constants
#define BB 2
#define SS 2048
#define DD 256
#define HH 8
#define DK 32
#define DV 32
#define DFF 512
#define NLAYER 2
#define MTOT (BB*SS)          // 4096
#define QKV3 (3*DD)           // 768

#define LOG2E 1.4426950408889634f
#define MV2L (-1e-30f * LOG2E)

// ---------------------------------------------------------------------------
// helpers
// ---------------------------------------------------------------------------
__device__ __forceinline__ uint32_t smem_u32(const void* p) {
    uint32_t a;
    asm("{ .reg .u64 tmp; cvta.to.shared.u64 tmp, %1; cvt.u32.u64 %0, tmp; }"
        : "=r"(a) : "l"(p));
    return a;
}

__device__ __forceinline__ void ldmatrix_x4(uint32_t& a0, uint32_t& a1,
                                            uint32_t& a2, uint32_t& a3,
                                            uint32_t addr) {
    asm volatile("ldmatrix.sync.aligned.m8n8.x4.shared.b16 {%0,%1,%2,%3}, [%4];"
                 : "=r"(a0), "=r"(a1), "=r"(a2), "=r"(a3) : "r"(addr));
}

__device__ __forceinline__ void ldmatrix_x2(uint32_t& b0, uint32_t& b1,
                                            uint32_t addr) {
    asm volatile("ldmatrix.sync.aligned.m8n8.x2.shared.b16 {%0,%1}, [%2];"
                 : "=r"(b0), "=r"(b1) : "r"(addr));
}

__device__ __forceinline__ void ldmatrix_x2_trans(uint32_t& b0, uint32_t& b1,
                                                  uint32_t addr) {
    asm volatile("ldmatrix.sync.aligned.m8n8.x2.trans.shared.b16 {%0,%1}, [%2];"
                 : "=r"(b0), "=r"(b1) : "r"(addr));
}

__device__ __forceinline__ void mma_16816(float* c, uint32_t a0, uint32_t a1,
                                          uint32_t a2, uint32_t a3,
                                          uint32_t b0, uint32_t b1) {
    asm volatile(
        "mma.sync.aligned.m16n8k16.row.col.f32.f16.f16.f32 "
        "{%0,%1,%2,%3}, {%4,%5,%6,%7}, {%8,%9}, {%0,%1,%2,%3};"
        : "+f"(c[0]), "+f"(c[1]), "+f"(c[2]), "+f"(c[3])
        : "r"(a0), "r"(a1), "r"(a2), "r"(a3), "r"(b0), "r"(b1));
}

__device__ __forceinline__ float ex2f(float x) {
    float r;
    asm("ex2.approx.f32 %0, %1;" : "=f"(r) : "f"(x));
    return r;
}

__device__ __forceinline__ uint32_t pack_h2(float lo, float hi) {
    __half2 v = __floats2half2_rn(lo, hi);   // x=lo lane, y=hi lane
    return *(uint32_t*)&v;
}

__device__ __forceinline__ void cp16(uint32_t dst, const void* src) {
    asm volatile("cp.async.cg.shared.global [%0], [%1], 16;" :: "r"(dst), "l"(src));
}
#define CP_COMMIT() asm volatile("cp.async.commit_group;" ::: "memory")
#define CP_WAIT(N)  asm volatile("cp.async.wait_group %0;" :: "n"(N) : "memory")

// ---------------------------------------------------------------------------
// Scratch (static device globals; no allocation)
// ---------------------------------------------------------------------------
__device__ float g_x[MTOT*DD];
__device__ float g_y[MTOT*DD];
__device__ __half g_xhi[MTOT*DD], g_xlo[MTOT*DD];
__device__ __half g_qkvhi[MTOT*QKV3], g_qkvlo[MTOT*QKV3];
__device__ __half g_ohi[MTOT*DD], g_olo[MTOT*DD];
__device__ __half g_hhi[MTOT*DFF], g_hlo[MTOT*DFF];
__device__ __half g_wqkvhi[NLAYER*QKV3*DD], g_wqkvlo[NLAYER*QKV3*DD];
__device__ __half g_wohi[NLAYER*DD*DD],   g_wolo[NLAYER*DD*DD];
__device__ __half g_w1hi[NLAYER*DFF*DD],  g_w1lo[NLAYER*DFF*DD];
__device__ __half g_w2hi[NLAYER*DD*DFF],  g_w2lo[NLAYER*DD*DFF];

__device__ __forceinline__ void split_store(float v, __half* hi, __half* lo,
                                            size_t idx) {
    __half h = __float2half_rn(v);
    hi[idx] = h;
    lo[idx] = __float2half_rn(v - __half2float(h));
}

// ---------------------------------------------------------------------------
// Input copy + split
// ---------------------------------------------------------------------------
__global__ void copy_kernel(const float* __restrict__ src) {
    size_t i = (size_t)blockIdx.x * blockDim.x + threadIdx.x;
    float v = src[i];
    g_x[i] = v;
    split_store(v, g_xhi, g_xlo, i);
}

// ---------------------------------------------------------------------------
// Weight packing (both layers per launch)
// ---------------------------------------------------------------------------
// QKV: out[l][n][d] = Wsel[l][h][d][k], n = sel*256 + h*32 + k
__global__ void pack_qkv_kernel(const float* __restrict__ Wq,
                                const float* __restrict__ Wk,
                                const float* __restrict__ Wv) {
    int layer = blockIdx.y;
    int idx = blockIdx.x * 256 + threadIdx.x;   // n*256 + d
    int n = idx >> 8, d = idx & 255;
    int sel = n >> 8;
    int r = n & 255;
    int h = r >> 5, kk = r & 31;
    const float* W = (sel == 0) ? Wq : (sel == 1) ? Wk : Wv;
    float v = W[(size_t)layer * HH * DD * DK + (h * DD + d) * DK + kk];
    split_store(v, g_wqkvhi, g_wqkvlo, (size_t)layer * QKV3 * DD + idx);
}

// transpose pack via smem tile: in [KK][NN] row-major -> out[n*KK + k]
__global__ void pack_wt_kernel(const float* __restrict__ W,
                               __half* __restrict__ hi, __half* __restrict__ lo,
                               int KK, int NN) {
    __shared__ float tile[32][33];
    int layer = blockIdx.z;
    W  += (size_t)layer * KK * NN;
    hi += (size_t)layer * KK * NN;
    lo += (size_t)layer * KK * NN;
    int k0 = blockIdx.x * 32, n0 = blockIdx.y * 32;
    int tx = threadIdx.x & 31, ty = threadIdx.x >> 5;   // 32 x 8
    #pragma unroll
    for (int l = 0; l < 4; l++) {
        int k = ty + l * 8;
        tile[k][tx] = W[(size_t)(k0 + k) * NN + n0 + tx];
    }
    __syncthreads();
    #pragma unroll
    for (int l = 0; l < 4; l++) {
        int n = ty + l * 8;
        float v = tile[tx][n];
        split_store(v, hi, lo, (size_t)(n0 + n) * KK + k0 + tx);
    }
}

// ---------------------------------------------------------------------------
// HMMA fp16-split GEMM (CTA 128x64, BK=32, 8 warps 4x2), cp.async 2-stage.
// A: [M][K] half row-major; B: [N][K] half row-major.
// ---------------------------------------------------------------------------
#define ASTR 40          // smem row stride in halves (80B)
#define G_A_HI 0
#define G_A_LO 10240
#define G_B_HI 20480
#define G_B_LO 25600
#define G_STG  30720
#define G_SMEM (2*G_STG)   // 61440

template<bool BIAS, bool RELU, bool RES, bool SPLIT, bool F32OUT, bool SCALEQ>
__global__ void __launch_bounds__(256)
hmma_gemm(const __half* __restrict__ Ahi, const __half* __restrict__ Alo,
          const __half* __restrict__ Bhi, const __half* __restrict__ Blo,
          const float* __restrict__ bias, const float* __restrict__ resp,
          float* __restrict__ C, __half* __restrict__ Chi,
          __half* __restrict__ Clo, int M, int N, int K) {
    extern __shared__ char smem[];
    uint32_t sb = smem_u32(smem);

    int t = threadIdx.x, wid = t >> 5, lane = t & 31;
    int warp_m = wid & 3;
    int warp_n = wid >> 2;
    int row0 = blockIdx.y * 128, col0 = blockIdx.x * 64;

    float acc[2][4][4];
    #pragma unroll
    for (int mt = 0; mt < 2; mt++)
        #pragma unroll
        for (int nt = 0; nt < 4; nt++)
            #pragma unroll
            for (int e = 0; e < 4; e++) acc[mt][nt][e] = 0.0f;

    int a_off = (warp_m * 32 + (lane & 15)) * ASTR + (lane >> 4) * 8;
    int b_off = (warp_n * 32 + (lane & 7))  * ASTR + ((lane >> 3) & 1) * 8;

    // stage loader
    auto load_stage = [&](int s, int kc) {
        uint32_t ub = sb + s * G_STG;
        #pragma unroll
        for (int l = 0; l < 2; l++) {
            int idx = t + l * 256;
            int r = idx >> 2, c4 = idx & 3;
            size_t gsrc = (size_t)(row0 + r) * K + kc + c4 * 8;
            cp16(ub + G_A_HI + r * 80 + c4 * 16, Ahi + gsrc);
            cp16(ub + G_A_LO + r * 80 + c4 * 16, Alo + gsrc);
        }
        {
            int r = t >> 2, c4 = t & 3;
            size_t gsrc = (size_t)(col0 + r) * K + kc + c4 * 8;
            cp16(ub + G_B_HI + r * 80 + c4 * 16, Bhi + gsrc);
            cp16(ub + G_B_LO + r * 80 + c4 * 16, Blo + gsrc);
        }
    };

    int nk = K >> 5;
    load_stage(0, 0);
    CP_COMMIT();

    for (int i = 0; i < nk; i++) {
        if (i + 1 < nk) { load_stage((i + 1) & 1, (i + 1) * 32); CP_COMMIT(); CP_WAIT(1); }
        else            { CP_WAIT(0); }
        __syncthreads();

        uint32_t stg = sb + (i & 1) * G_STG;
        #pragma unroll
        for (int s = 0; s < 3; s++) {
            uint32_t baseA = stg + ((s == 2) ? G_A_LO : G_A_HI);
            uint32_t baseB = stg + ((s == 1) ? G_B_LO : G_B_HI);
            #pragma unroll
            for (int kk = 0; kk < 32; kk += 16) {
                uint32_t afr[2][4];
                #pragma unroll
                for (int mt = 0; mt < 2; mt++)
                    ldmatrix_x4(afr[mt][0], afr[mt][1], afr[mt][2], afr[mt][3],
                                baseA + (uint32_t)(a_off + mt * 16 * ASTR + kk) * 2);
                uint32_t bfr[4][2];
                #pragma unroll
                for (int nt = 0; nt < 4; nt++)
                    ldmatrix_x2(bfr[nt][0], bfr[nt][1],
                                baseB + (uint32_t)(b_off + nt * 8 * ASTR + kk) * 2);
                #pragma unroll
                for (int mt = 0; mt < 2; mt++)
                    #pragma unroll
                    for (int nt = 0; nt < 4; nt++)
                        mma_16816(acc[mt][nt], afr[mt][0], afr[mt][1], afr[mt][2],
                                  afr[mt][3], bfr[nt][0], bfr[nt][1]);
            }
        }
        __syncthreads();
    }

    #pragma unroll
    for (int mt = 0; mt < 2; mt++) {
        int r_lo = row0 + warp_m * 32 + mt * 16 + (lane >> 2);
        #pragma unroll
        for (int nt = 0; nt < 4; nt++) {
            int c = col0 + warp_n * 32 + nt * 8 + (lane & 3) * 2;
            #pragma unroll
            for (int half = 0; half < 2; half++) {
                int r = r_lo + half * 8;
                size_t rb = (size_t)r * N;
                #pragma unroll
                for (int e = 0; e < 2; e++) {
                    float v = acc[mt][nt][half * 2 + e];
                    int col = c + e;
                    if (BIAS) v += bias[col];
                    if (RELU) v = fmaxf(v, 0.0f);
                    if (RES)  v += resp[rb + col];
                    if (SCALEQ) { if (col < DD) v *= LOG2E; }
                    if (F32OUT) C[rb + col] = v;
                    if (SPLIT)  split_store(v, Chi, Clo, rb + col);
                }
            }
        }
    }
}

// ---------------------------------------------------------------------------
// HMMA flash attention, fp16 splits, cp.async 2-stage KV pipeline.
// 128 queries/CTA, 64-key tiles, 4 warps. q pre-scaled by log2e.
// QK: 3 passes (Qhi Khi, Qhi Klo, Qlo Khi). PV: P fp16 x (Vhi + Vlo).
// ---------------------------------------------------------------------------
#define ATT_Q_HI 0
#define ATT_Q_LO 10240
#define ATT_KV0  20480            // + stage*20480 + which*5120
#define ATT_KSTG 20480
#define ATT_M0   61440            // + stage*256 (64 floats)
#define ATT_SMEM 61952

__global__ void __launch_bounds__(128) attention_hmma(const float* __restrict__ mask) {
    extern __shared__ char smem[];
    uint32_t sb = smem_u32(smem);

    int b = blockIdx.y >> 3, h = blockIdx.y & 7;
    int t = threadIdx.x, warp = t >> 5, lane = t & 31;
    int row0 = blockIdx.x * 128;

    // KV stage loader (cp.async) + mask (regular)
    auto load_kv = [&](int s, int t0) {
        uint32_t ub = sb + ATT_KV0 + s * ATT_KSTG;
        #pragma unroll
        for (int l = 0; l < 8; l++) {
            int idx = t + l * 128;
            int r = idx >> 4, which = (idx >> 2) & 3, c4 = idx & 3;
            const __half* src = (which & 1) ? g_qkvlo : g_qkvhi;
            int coff = ((which < 2) ? DD : 2 * DD) + h * DK + c4 * 8;
            cp16(ub + which * 5120 + r * 80 + c4 * 16,
                 src + (size_t)(b * SS + t0 + r) * QKV3 + coff);
        }
        if (t < 64)
            *(float*)(smem + ATT_M0 + s * 256 + t * 4) = mask[b * SS + t0 + t];
    };

    load_kv(0, 0);
    CP_COMMIT();

    // load Q tile (hi/lo) with regular loads
    {
        size_t qbase = (size_t)(b * SS + row0) * QKV3 + h * DK;
        #pragma unroll
        for (int l = 0; l < 8; l++) {
            int idx = t + l * 128;
            int r = idx >> 3, which = (idx >> 2) & 1, c4 = idx & 3;
            const __half* src = which ? g_qkvlo : g_qkvhi;
            *(uint4*)(smem + (which ? ATT_Q_LO : ATT_Q_HI) + r * 80 + c4 * 16) =
                *(const uint4*)&src[qbase + (size_t)r * QKV3 + c4 * 8];
        }
    }
    __syncthreads();

    // Q fragments persist in regs
    uint32_t qf[2][2][2][4];   // [hi/lo][mt][kstep][4]
    {
        int a_off = (warp * 32 + (lane & 15)) * ASTR + (lane >> 4) * 8;
        #pragma unroll
        for (int w2 = 0; w2 < 2; w2++) {
            uint32_t base = sb + (w2 ? ATT_Q_LO : ATT_Q_HI);
            #pragma unroll
            for (int mt = 0; mt < 2; mt++)
                #pragma unroll
                for (int ks = 0; ks < 2; ks++)
                    ldmatrix_x4(qf[w2][mt][ks][0], qf[w2][mt][ks][1],
                                qf[w2][mt][ks][2], qf[w2][mt][ks][3],
                                base + (uint32_t)(a_off + mt * 16 * ASTR + ks * 16) * 2);
        }
    }

    float m_run[2][2], l_run[2][2], oacc[2][4][4];
    #pragma unroll
    for (int mt = 0; mt < 2; mt++) {
        #pragma unroll
        for (int hf = 0; hf < 2; hf++) { m_run[mt][hf] = -1e30f; l_run[mt][hf] = 0.f; }
        #pragma unroll
        for (int nt = 0; nt < 4; nt++)
            #pragma unroll
            for (int e = 0; e < 4; e++) oacc[mt][nt][e] = 0.f;
    }

    const int ntiles = SS / 64;
    for (int i = 0; i < ntiles; i++) {
        if (i + 1 < ntiles) { load_kv((i + 1) & 1, (i + 1) * 64); CP_COMMIT(); CP_WAIT(1); }
        else                { CP_WAIT(0); }
        __syncthreads();

        uint32_t kvstg = sb + ATT_KV0 + (i & 1) * ATT_KSTG;
        const float* sM = (const float*)(smem + ATT_M0 + (i & 1) * 256);

        // S = Q K^T (3 split passes)
        float sc[2][8][4];
        #pragma unroll
        for (int mt = 0; mt < 2; mt++)
            #pragma unroll
            for (int nt = 0; nt < 8; nt++)
                #pragma unroll
                for (int e = 0; e < 4; e++) sc[mt][nt][e] = 0.f;
        {
            int b_off = (lane & 7) * ASTR + ((lane >> 3) & 1) * 8;
            #pragma unroll
            for (int s = 0; s < 3; s++) {
                int wa = (s == 2) ? 1 : 0;
                uint32_t kbase = kvstg + ((s == 1) ? 5120 : 0);
                #pragma unroll
                for (int ks = 0; ks < 2; ks++)
                    #pragma unroll
                    for (int nt = 0; nt < 8; nt++) {
                        uint32_t b0, b1;
                        ldmatrix_x2(b0, b1,
                            kbase + (uint32_t)(b_off + nt * 8 * ASTR + ks * 16) * 2);
                        mma_16816(sc[0][nt], qf[wa][0][ks][0], qf[wa][0][ks][1],
                                  qf[wa][0][ks][2], qf[wa][0][ks][3], b0, b1);
                        mma_16816(sc[1][nt], qf[wa][1][ks][0], qf[wa][1][ks][1],
                                  qf[wa][1][ks][2], qf[wa][1][ks][3], b0, b1);
                    }
            }
        }

        // mask + tile max
        float tmax[2][2] = {{-1e30f, -1e30f}, {-1e30f, -1e30f}};
        #pragma unroll
        for (int nt = 0; nt < 8; nt++) {
            int c0 = nt * 8 + (lane & 3) * 2;
            float mvA = sM[c0], mvB = sM[c0 + 1];
            float cA = (1.f - mvA) * MV2L, cB = (1.f - mvB) * MV2L;
            #pragma unroll
            for (int mt = 0; mt < 2; mt++) {
                sc[mt][nt][0] = fmaf(mvA, sc[mt][nt][0], cA);
                sc[mt][nt][1] = fmaf(mvB, sc[mt][nt][1], cB);
                sc[mt][nt][2] = fmaf(mvA, sc[mt][nt][2], cA);
                sc[mt][nt][3] = fmaf(mvB, sc[mt][nt][3], cB);
                tmax[mt][0] = fmaxf(tmax[mt][0], fmaxf(sc[mt][nt][0], sc[mt][nt][1]));
                tmax[mt][1] = fmaxf(tmax[mt][1], fmaxf(sc[mt][nt][2], sc[mt][nt][3]));
            }
        }
        float corr[2][2];
        #pragma unroll
        for (int mt = 0; mt < 2; mt++)
            #pragma unroll
            for (int hf = 0; hf < 2; hf++) {
                float v = tmax[mt][hf];
                v = fmaxf(v, __shfl_xor_sync(0xffffffffu, v, 1));
                v = fmaxf(v, __shfl_xor_sync(0xffffffffu, v, 2));
                float mn = fmaxf(m_run[mt][hf], v);
                corr[mt][hf] = ex2f(m_run[mt][hf] - mn);
                m_run[mt][hf] = mn;
                l_run[mt][hf] *= corr[mt][hf];
            }
        #pragma unroll
        for (int mt = 0; mt < 2; mt++)
            #pragma unroll
            for (int nt = 0; nt < 4; nt++)
                #pragma unroll
                for (int e = 0; e < 4; e++)
                    oacc[mt][nt][e] *= corr[mt][e >> 1];

        // p = exp2(sc - m) -> fp16 A-fragments
        uint32_t pf[2][4][4];
        #pragma unroll
        for (int mt = 0; mt < 2; mt++)
            #pragma unroll
            for (int nt = 0; nt < 8; nt++) {
                float p0 = ex2f(sc[mt][nt][0] - m_run[mt][0]);
                float p1 = ex2f(sc[mt][nt][1] - m_run[mt][0]);
                float p2 = ex2f(sc[mt][nt][2] - m_run[mt][1]);
                float p3 = ex2f(sc[mt][nt][3] - m_run[mt][1]);
                l_run[mt][0] += p0 + p1;
                l_run[mt][1] += p2 + p3;
                int kb = nt >> 1, hi2 = (nt & 1) * 2;
                pf[mt][kb][hi2 + 0] = pack_h2(p0, p1);
                pf[mt][kb][hi2 + 1] = pack_h2(p2, p3);
            }

        // O += P @ V   (Vhi + Vlo passes)
        #pragma unroll
        for (int s = 0; s < 2; s++) {
            uint32_t vbase = kvstg + (2 + s) * 5120;
            #pragma unroll
            for (int kb = 0; kb < 4; kb++) {
                uint32_t vrow = vbase + (uint32_t)((kb * 16 + (lane & 15)) * ASTR) * 2;
                #pragma unroll
                for (int nt = 0; nt < 4; nt++) {
                    uint32_t b0, b1;
                    ldmatrix_x2_trans(b0, b1, vrow + (uint32_t)(nt * 8) * 2);
                    mma_16816(oacc[0][nt], pf[0][kb][0], pf[0][kb][1],
                              pf[0][kb][2], pf[0][kb][3], b0, b1);
                    mma_16816(oacc[1][nt], pf[1][kb][0], pf[1][kb][1],
                              pf[1][kb][2], pf[1][kb][3], b0, b1);
                }
            }
        }
        __syncthreads();
    }

    // finalize
    #pragma unroll
    for (int mt = 0; mt < 2; mt++)
        #pragma unroll
        for (int hf = 0; hf < 2; hf++) {
            float v = l_run[mt][hf];
            v += __shfl_xor_sync(0xffffffffu, v, 1);
            v += __shfl_xor_sync(0xffffffffu, v, 2);
            l_run[mt][hf] = 1.0f / v;
        }
    #pragma unroll
    for (int mt = 0; mt < 2; mt++)
        #pragma unroll
        for (int hf = 0; hf < 2; hf++) {
            int row = row0 + warp * 32 + mt * 16 + (lane >> 2) + hf * 8;
            size_t obase = (size_t)(b * SS + row) * DD + h * DV;
            float inv = l_run[mt][hf];
            #pragma unroll
            for (int nt = 0; nt < 4; nt++) {
                int col = nt * 8 + (lane & 3) * 2;
                split_store(oacc[mt][nt][hf * 2 + 0] * inv, g_ohi, g_olo, obase + col);
                split_store(oacc[mt][nt][hf * 2 + 1] * inv, g_ohi, g_olo, obase + col + 1);
            }
        }
}

// ---------------------------------------------------------------------------
// LayerNorm (+ optional fp16 hi/lo split output)
// ---------------------------------------------------------------------------
__global__ void ln_kernel(const float* __restrict__ in, float* __restrict__ out,
                          __half* __restrict__ hi, __half* __restrict__ lo,
                          const float* __restrict__ gamma,
                          const float* __restrict__ beta, int gi) {
    int row = blockIdx.x;
    int t = threadIdx.x;
    float v = in[(size_t)row * DD + t];

    __shared__ float sred[8];

    float sum = v;
    #pragma unroll
    for (int off = 16; off > 0; off >>= 1) sum += __shfl_xor_sync(0xffffffffu, sum, off);
    if ((t & 31) == 0) sred[t >> 5] = sum;
    __syncthreads();
    float tot = 0.0f;
    #pragma unroll
    for (int i = 0; i < 8; i++) tot += sred[i];
    float mean = tot * (1.0f / DD);
    __syncthreads();

    float d0 = v - mean;
    float s2 = d0 * d0;
    #pragma unroll
    for (int off = 16; off > 0; off >>= 1) s2 += __shfl_xor_sync(0xffffffffu, s2, off);
    if ((t & 31) == 0) sred[t >> 5] = s2;
    __syncthreads();
    float tot2 = 0.0f;
    #pragma unroll
    for (int i = 0; i < 8; i++) tot2 += sred[i];
    float var = tot2 * (1.0f / DD);

    float g = gamma[gi], bb = beta[gi];
    float r = d0 * rsqrtf(var + 1e-14f) * g + bb;
    size_t idx = (size_t)row * DD + t;
    out[idx] = r;
    if (hi) split_store(r, hi, lo, idx);
}

// ---------------------------------------------------------------------------
// launch
// ---------------------------------------------------------------------------
extern "C" void kernel_launch(void* const* d_in, const int* in_sizes, int n_in,
                              void* d_out, int out_size) {
    const float* x     = (const float*)d_in[0];
    const float* mask  = (const float*)d_in[1];
    const float* Wq    = (const float*)d_in[2];
    const float* Wk    = (const float*)d_in[3];
    const float* Wv    = (const float*)d_in[4];
    const float* Wo    = (const float*)d_in[5];
    const float* W1    = (const float*)d_in[6];
    const float* b1    = (const float*)d_in[7];
    const float* W2    = (const float*)d_in[8];
    const float* b2    = (const float*)d_in[9];
    const float* gamma = (const float*)d_in[10];
    const float* beta  = (const float*)d_in[11];
    float* out = (float*)d_out;
    (void)in_sizes; (void)n_in; (void)out_size;

    float *p_x, *p_y;
    __half *p_xhi, *p_xlo, *p_ohi, *p_olo, *p_hhi, *p_hlo;
    __half *p_qkvhi, *p_qkvlo;
    __half *p_wqkvhi, *p_wqkvlo, *p_wohi, *p_wolo, *p_w1hi, *p_w1lo, *p_w2hi, *p_w2lo;
    cudaGetSymbolAddress((void**)&p_x, g_x);
    cudaGetSymbolAddress((void**)&p_y, g_y);
    cudaGetSymbolAddress((void**)&p_xhi, g_xhi);
    cudaGetSymbolAddress((void**)&p_xlo, g_xlo);
    cudaGetSymbolAddress((void**)&p_qkvhi, g_qkvhi);
    cudaGetSymbolAddress((void**)&p_qkvlo, g_qkvlo);
    cudaGetSymbolAddress((void**)&p_ohi, g_ohi);
    cudaGetSymbolAddress((void**)&p_olo, g_olo);
    cudaGetSymbolAddress((void**)&p_hhi, g_hhi);
    cudaGetSymbolAddress((void**)&p_hlo, g_hlo);
    cudaGetSymbolAddress((void**)&p_wqkvhi, g_wqkvhi);
    cudaGetSymbolAddress((void**)&p_wqkvlo, g_wqkvlo);
    cudaGetSymbolAddress((void**)&p_wohi, g_wohi);
    cudaGetSymbolAddress((void**)&p_wolo, g_wolo);
    cudaGetSymbolAddress((void**)&p_w1hi, g_w1hi);
    cudaGetSymbolAddress((void**)&p_w1lo, g_w1lo);
    cudaGetSymbolAddress((void**)&p_w2hi, g_w2hi);
    cudaGetSymbolAddress((void**)&p_w2lo, g_w2lo);

    // dynamic smem limits (idempotent host-side attribute sets)
    cudaFuncSetAttribute(hmma_gemm<false,false,false,true,false,true>,
                         cudaFuncAttributeMaxDynamicSharedMemorySize, G_SMEM);
    cudaFuncSetAttribute(hmma_gemm<false,false,true,false,true,false>,
                         cudaFuncAttributeMaxDynamicSharedMemorySize, G_SMEM);
    cudaFuncSetAttribute(hmma_gemm<true,true,false,true,false,false>,
                         cudaFuncAttributeMaxDynamicSharedMemorySize, G_SMEM);
    cudaFuncSetAttribute(hmma_gemm<true,false,true,false,true,false>,
                         cudaFuncAttributeMaxDynamicSharedMemorySize, G_SMEM);
    cudaFuncSetAttribute(attention_hmma,
                         cudaFuncAttributeMaxDynamicSharedMemorySize, ATT_SMEM);

    copy_kernel<<<MTOT, DD>>>(x);

    // pack all weights for both layers up front
    pack_qkv_kernel<<<dim3(QKV3 * DD / 256, NLAYER), 256>>>(Wq, Wk, Wv);
    pack_wt_kernel<<<dim3(DD/32, DD/32, NLAYER), 256>>>(Wo, p_wohi, p_wolo, DD, DD);
    pack_wt_kernel<<<dim3(DD/32, DFF/32, NLAYER), 256>>>(W1, p_w1hi, p_w1lo, DD, DFF);
    pack_wt_kernel<<<dim3(DFF/32, DD/32, NLAYER), 256>>>(W2, p_w2hi, p_w2lo, DFF, DD);

    for (int i = 0; i < NLAYER; i++) {
        // qkv = x @ Wqkv  (split fp16 out; q columns scaled by log2e)
        hmma_gemm<false,false,false,true,false,true><<<dim3(QKV3/64, MTOT/128), 256, G_SMEM>>>(
            p_xhi, p_xlo,
            p_wqkvhi + (size_t)i * QKV3 * DD, p_wqkvlo + (size_t)i * QKV3 * DD,
            nullptr, nullptr, nullptr, p_qkvhi, p_qkvlo, MTOT, QKV3, DD);

        // flash attention -> o split fp16
        attention_hmma<<<dim3(SS/128, BB*HH), 128, ATT_SMEM>>>(mask);

        // y = x + o @ Wo
        hmma_gemm<false,false,true,false,true,false><<<dim3(DD/64, MTOT/128), 256, G_SMEM>>>(
            p_ohi, p_olo,
            p_wohi + (size_t)i * DD * DD, p_wolo + (size_t)i * DD * DD,
            nullptr, p_x, p_y, nullptr, nullptr, MTOT, DD, DD);

        ln_kernel<<<MTOT, DD>>>(p_y, p_x, p_xhi, p_xlo, gamma, beta, 2*i);

        // h = relu(x @ W1 + b1) -> split fp16
        hmma_gemm<true,true,false,true,false,false><<<dim3(DFF/64, MTOT/128), 256, G_SMEM>>>(
            p_xhi, p_xlo,
            p_w1hi + (size_t)i * DFF * DD, p_w1lo + (size_t)i * DFF * DD,
            b1 + (size_t)i * DFF, nullptr, nullptr, p_hhi, p_hlo, MTOT, DFF, DD);

        // y = x + h @ W2 + b2
        hmma_gemm<true,false,true,false,true,false><<<dim3(DD/64, MTOT/128), 256, G_SMEM>>>(
            p_hhi, p_hlo,
            p_w2hi + (size_t)i * DD * DFF, p_w2lo + (size_t)i * DD * DFF,
            b2 + (size_t)i * DD, p_x, p_y, nullptr, nullptr, MTOT, DD, DFF);

        if (i == NLAYER - 1) {
            ln_kernel<<<MTOT, DD>>>(p_y, out, nullptr, nullptr, gamma, beta, 2*i+1);
        } else {
            ln_kernel<<<MTOT, DD>>>(p_y, p_x, p_xhi, p_xlo, gamma, beta, 2*i+1);
        }
    }
}

// round 6
// speedup vs baseline: 3.2585x; 1.2355x over previous
#include <cuda_runtime.h>
#include <cuda_fp16.h>
#include <cstdint>
#include <math.h>

// Problem constants
#define BB 2
#define SS 2048
#define DD 256
#define HH 8
#define DK 32
#define DV 32
#define DFF 512
#define NLAYER 2
#define MTOT (BB*SS)          // 4096
#define QKV3 (3*DD)           // 768

#define LOG2E 1.4426950408889634f
#define MV2L (-1e-30f * LOG2E)

// ---------------------------------------------------------------------------
// helpers
// ---------------------------------------------------------------------------
__device__ __forceinline__ uint32_t smem_u32(const void* p) {
    uint32_t a;
    asm("{ .reg .u64 tmp; cvta.to.shared.u64 tmp, %1; cvt.u32.u64 %0, tmp; }"
        : "=r"(a) : "l"(p));
    return a;
}

__device__ __forceinline__ void ldmatrix_x4(uint32_t& a0, uint32_t& a1,
                                            uint32_t& a2, uint32_t& a3,
                                            uint32_t addr) {
    asm volatile("ldmatrix.sync.aligned.m8n8.x4.shared.b16 {%0,%1,%2,%3}, [%4];"
                 : "=r"(a0), "=r"(a1), "=r"(a2), "=r"(a3) : "r"(addr));
}

__device__ __forceinline__ void ldmatrix_x2(uint32_t& b0, uint32_t& b1,
                                            uint32_t addr) {
    asm volatile("ldmatrix.sync.aligned.m8n8.x2.shared.b16 {%0,%1}, [%2];"
                 : "=r"(b0), "=r"(b1) : "r"(addr));
}

__device__ __forceinline__ void ldmatrix_x2_trans(uint32_t& b0, uint32_t& b1,
                                                  uint32_t addr) {
    asm volatile("ldmatrix.sync.aligned.m8n8.x2.trans.shared.b16 {%0,%1}, [%2];"
                 : "=r"(b0), "=r"(b1) : "r"(addr));
}

__device__ __forceinline__ void mma_16816(float* c, uint32_t a0, uint32_t a1,
                                          uint32_t a2, uint32_t a3,
                                          uint32_t b0, uint32_t b1) {
    asm volatile(
        "mma.sync.aligned.m16n8k16.row.col.f32.f16.f16.f32 "
        "{%0,%1,%2,%3}, {%4,%5,%6,%7}, {%8,%9}, {%0,%1,%2,%3};"
        : "+f"(c[0]), "+f"(c[1]), "+f"(c[2]), "+f"(c[3])
        : "r"(a0), "r"(a1), "r"(a2), "r"(a3), "r"(b0), "r"(b1));
}

__device__ __forceinline__ float ex2f(float x) {
    float r;
    asm("ex2.approx.f32 %0, %1;" : "=f"(r) : "f"(x));
    return r;
}

__device__ __forceinline__ uint32_t pack_h2(float lo, float hi) {
    __half2 v = __floats2half2_rn(lo, hi);
    return *(uint32_t*)&v;
}

__device__ __forceinline__ void cp16(uint32_t dst, const void* src) {
    asm volatile("cp.async.cg.shared.global [%0], [%1], 16;" :: "r"(dst), "l"(src));
}
#define CP_COMMIT() asm volatile("cp.async.commit_group;" ::: "memory")
#define CP_WAIT(N)  asm volatile("cp.async.wait_group %0;" :: "n"(N) : "memory")

// ---------------------------------------------------------------------------
// Scratch (static device globals; no allocation)
// ---------------------------------------------------------------------------
__device__ float g_x[MTOT*DD];
__device__ __half g_xhi[MTOT*DD], g_xlo[MTOT*DD];
__device__ __half g_qkvhi[MTOT*QKV3], g_qkvlo[MTOT*QKV3];
__device__ __half g_ohi[MTOT*DD], g_olo[MTOT*DD];
__device__ __half g_hhi[MTOT*DFF], g_hlo[MTOT*DFF];
__device__ __half g_wqkvhi[NLAYER*QKV3*DD], g_wqkvlo[NLAYER*QKV3*DD];
__device__ __half g_wohi[NLAYER*DD*DD],   g_wolo[NLAYER*DD*DD];
__device__ __half g_w1hi[NLAYER*DFF*DD],  g_w1lo[NLAYER*DFF*DD];
__device__ __half g_w2hi[NLAYER*DD*DFF],  g_w2lo[NLAYER*DD*DFF];

__device__ __forceinline__ void split_store(float v, __half* hi, __half* lo,
                                            size_t idx) {
    __half h = __float2half_rn(v);
    hi[idx] = h;
    lo[idx] = __float2half_rn(v - __half2float(h));
}

// split two adjacent values with half2 stores (idx must be even-aligned)
__device__ __forceinline__ void split_store2(float v0, float v1, __half* hi,
                                             __half* lo, size_t idx) {
    __half h0 = __float2half_rn(v0), h1 = __float2half_rn(v1);
    *(__half2*)&hi[idx] = __halves2half2(h0, h1);
    *(__half2*)&lo[idx] = __halves2half2(
        __float2half_rn(v0 - __half2float(h0)),
        __float2half_rn(v1 - __half2float(h1)));
}

// ---------------------------------------------------------------------------
// Input copy + split
// ---------------------------------------------------------------------------
__global__ void copy_kernel(const float* __restrict__ src) {
    size_t i = (size_t)blockIdx.x * blockDim.x + threadIdx.x;
    float v = src[i];
    g_x[i] = v;
    split_store(v, g_xhi, g_xlo, i);
}

// ---------------------------------------------------------------------------
// Weight packing (both layers per launch)
// ---------------------------------------------------------------------------
__global__ void pack_qkv_kernel(const float* __restrict__ Wq,
                                const float* __restrict__ Wk,
                                const float* __restrict__ Wv) {
    int layer = blockIdx.y;
    int idx = blockIdx.x * 256 + threadIdx.x;   // n*256 + d
    int n = idx >> 8, d = idx & 255;
    int sel = n >> 8;
    int r = n & 255;
    int h = r >> 5, kk = r & 31;
    const float* W = (sel == 0) ? Wq : (sel == 1) ? Wk : Wv;
    float v = W[(size_t)layer * HH * DD * DK + (h * DD + d) * DK + kk];
    split_store(v, g_wqkvhi, g_wqkvlo, (size_t)layer * QKV3 * DD + idx);
}

__global__ void pack_wt_kernel(const float* __restrict__ W,
                               __half* __restrict__ hi, __half* __restrict__ lo,
                               int KK, int NN) {
    __shared__ float tile[32][33];
    int layer = blockIdx.z;
    W  += (size_t)layer * KK * NN;
    hi += (size_t)layer * KK * NN;
    lo += (size_t)layer * KK * NN;
    int k0 = blockIdx.x * 32, n0 = blockIdx.y * 32;
    int tx = threadIdx.x & 31, ty = threadIdx.x >> 5;
    #pragma unroll
    for (int l = 0; l < 4; l++) {
        int k = ty + l * 8;
        tile[k][tx] = W[(size_t)(k0 + k) * NN + n0 + tx];
    }
    __syncthreads();
    #pragma unroll
    for (int l = 0; l < 4; l++) {
        int n = ty + l * 8;
        float v = tile[tx][n];
        split_store(v, hi, lo, (size_t)(n0 + n) * KK + k0 + tx);
    }
}

// ---------------------------------------------------------------------------
// HMMA fp16-split GEMM (CTA 128x64, BK=32, 8 warps 4x2), cp.async 2-stage.
// Split fp16 output only. Used for QKV and W1.
// ---------------------------------------------------------------------------
#define ASTR 40
#define G_A_HI 0
#define G_A_LO 10240
#define G_B_HI 20480
#define G_B_LO 25600
#define G_STG  30720
#define G_SMEM (2*G_STG)   // 61440

template<bool BIAS, bool RELU, bool SCALEQ>
__global__ void __launch_bounds__(256)
hmma_gemm(const __half* __restrict__ Ahi, const __half* __restrict__ Alo,
          const __half* __restrict__ Bhi, const __half* __restrict__ Blo,
          const float* __restrict__ bias,
          __half* __restrict__ Chi, __half* __restrict__ Clo,
          int M, int N, int K) {
    extern __shared__ char smem[];
    uint32_t sb = smem_u32(smem);

    int t = threadIdx.x, wid = t >> 5, lane = t & 31;
    int warp_m = wid & 3;
    int warp_n = wid >> 2;
    int row0 = blockIdx.y * 128, col0 = blockIdx.x * 64;

    float acc[2][4][4];
    #pragma unroll
    for (int mt = 0; mt < 2; mt++)
        #pragma unroll
        for (int nt = 0; nt < 4; nt++)
            #pragma unroll
            for (int e = 0; e < 4; e++) acc[mt][nt][e] = 0.0f;

    int a_off = (warp_m * 32 + (lane & 15)) * ASTR + (lane >> 4) * 8;
    int b_off = (warp_n * 32 + (lane & 7))  * ASTR + ((lane >> 3) & 1) * 8;

    auto load_stage = [&](int s, int kc) {
        uint32_t ub = sb + s * G_STG;
        #pragma unroll
        for (int l = 0; l < 2; l++) {
            int idx = t + l * 256;
            int r = idx >> 2, c4 = idx & 3;
            size_t gsrc = (size_t)(row0 + r) * K + kc + c4 * 8;
            cp16(ub + G_A_HI + r * 80 + c4 * 16, Ahi + gsrc);
            cp16(ub + G_A_LO + r * 80 + c4 * 16, Alo + gsrc);
        }
        {
            int r = t >> 2, c4 = t & 3;
            size_t gsrc = (size_t)(col0 + r) * K + kc + c4 * 8;
            cp16(ub + G_B_HI + r * 80 + c4 * 16, Bhi + gsrc);
            cp16(ub + G_B_LO + r * 80 + c4 * 16, Blo + gsrc);
        }
    };

    int nk = K >> 5;
    load_stage(0, 0);
    CP_COMMIT();

    for (int i = 0; i < nk; i++) {
        if (i + 1 < nk) { load_stage((i + 1) & 1, (i + 1) * 32); CP_COMMIT(); CP_WAIT(1); }
        else            { CP_WAIT(0); }
        __syncthreads();

        uint32_t stg = sb + (i & 1) * G_STG;
        #pragma unroll
        for (int s = 0; s < 3; s++) {
            uint32_t baseA = stg + ((s == 2) ? G_A_LO : G_A_HI);
            uint32_t baseB = stg + ((s == 1) ? G_B_LO : G_B_HI);
            #pragma unroll
            for (int kk = 0; kk < 32; kk += 16) {
                uint32_t afr[2][4];
                #pragma unroll
                for (int mt = 0; mt < 2; mt++)
                    ldmatrix_x4(afr[mt][0], afr[mt][1], afr[mt][2], afr[mt][3],
                                baseA + (uint32_t)(a_off + mt * 16 * ASTR + kk) * 2);
                uint32_t bfr[4][2];
                #pragma unroll
                for (int nt = 0; nt < 4; nt++)
                    ldmatrix_x2(bfr[nt][0], bfr[nt][1],
                                baseB + (uint32_t)(b_off + nt * 8 * ASTR + kk) * 2);
                #pragma unroll
                for (int mt = 0; mt < 2; mt++)
                    #pragma unroll
                    for (int nt = 0; nt < 4; nt++)
                        mma_16816(acc[mt][nt], afr[mt][0], afr[mt][1], afr[mt][2],
                                  afr[mt][3], bfr[nt][0], bfr[nt][1]);
            }
        }
        __syncthreads();
    }

    #pragma unroll
    for (int mt = 0; mt < 2; mt++) {
        int r_lo = row0 + warp_m * 32 + mt * 16 + (lane >> 2);
        #pragma unroll
        for (int nt = 0; nt < 4; nt++) {
            int c = col0 + warp_n * 32 + nt * 8 + (lane & 3) * 2;
            #pragma unroll
            for (int half = 0; half < 2; half++) {
                int r = r_lo + half * 8;
                size_t rb = (size_t)r * N;
                float v0 = acc[mt][nt][half * 2 + 0];
                float v1 = acc[mt][nt][half * 2 + 1];
                if (BIAS) { v0 += bias[c]; v1 += bias[c + 1]; }
                if (RELU) { v0 = fmaxf(v0, 0.0f); v1 = fmaxf(v1, 0.0f); }
                if (SCALEQ) { if (c < DD) { v0 *= LOG2E; v1 *= LOG2E; } }
                split_store2(v0, v1, Chi, Clo, rb + c);
            }
        }
    }
}

// ---------------------------------------------------------------------------
// GEMM + residual + LayerNorm fused (Wo and W2 paths).
// Tile 32 x 256 (full row), K in {256,512}, 8 warps (2 along M x 4 along N).
// Epilogue: fp32 rows staged in smem, warp-per-row LN, writes fp32 x (or out)
// and optionally fp16 hi/lo splits.
// ---------------------------------------------------------------------------
#define LG_A_HI 0
#define LG_A_LO 2560
#define LG_B_HI 5120
#define LG_B_LO 25600
#define LG_STG  46080
#define LG_SMEM (2*LG_STG)   // 92160 (epilogue fp32 buffer 32KB aliases stage 0)

template<bool BIAS, bool SPLITOUT>
__global__ void __launch_bounds__(256)
ln_gemm(const __half* __restrict__ Ahi, const __half* __restrict__ Alo,
        const __half* __restrict__ Bhi, const __half* __restrict__ Blo,
        const float* __restrict__ bias, const float* __restrict__ resp,
        float* __restrict__ xout, __half* __restrict__ Xhi,
        __half* __restrict__ Xlo, const float* __restrict__ gamma,
        const float* __restrict__ beta, int gi, int K) {
    extern __shared__ char smem[];
    uint32_t sb = smem_u32(smem);

    int t = threadIdx.x, wid = t >> 5, lane = t & 31;
    int warp_m = wid & 1;        // 0..1 (16 rows)
    int warp_n = wid >> 1;       // 0..3 (64 cols)
    int row0 = blockIdx.x * 32;

    float acc[8][4];
    #pragma unroll
    for (int nt = 0; nt < 8; nt++)
        #pragma unroll
        for (int e = 0; e < 4; e++) acc[nt][e] = 0.0f;

    int a_off = (warp_m * 16 + (lane & 15)) * ASTR + (lane >> 4) * 8;
    int b_lane = (lane & 7) * ASTR + ((lane >> 3) & 1) * 8;

    auto load_stage = [&](int s, int kc) {
        uint32_t ub = sb + s * LG_STG;
        {   // A: 32 rows x 32 cols x hi/lo = 256 cp16
            int idx = t;
            int r = idx >> 3, which = (idx >> 2) & 1, c4 = idx & 3;
            size_t gsrc = (size_t)(row0 + r) * K + kc + c4 * 8;
            cp16(ub + (which ? LG_A_LO : LG_A_HI) + r * 80 + c4 * 16,
                 (which ? Alo : Ahi) + gsrc);
        }
        #pragma unroll
        for (int l = 0; l < 8; l++) {   // B: 256 rows x 32 x hi/lo = 2048 cp16
            int idx = t + l * 256;
            int r = idx >> 3, which = (idx >> 2) & 1, c4 = idx & 3;
            size_t gsrc = (size_t)r * K + kc + c4 * 8;
            cp16(ub + (which ? LG_B_LO : LG_B_HI) + r * 80 + c4 * 16,
                 (which ? Blo : Bhi) + gsrc);
        }
    };

    int nk = K >> 5;
    load_stage(0, 0);
    CP_COMMIT();

    for (int i = 0; i < nk; i++) {
        if (i + 1 < nk) { load_stage((i + 1) & 1, (i + 1) * 32); CP_COMMIT(); CP_WAIT(1); }
        else            { CP_WAIT(0); }
        __syncthreads();

        uint32_t stg = sb + (i & 1) * LG_STG;
        #pragma unroll
        for (int s = 0; s < 3; s++) {
            uint32_t baseA = stg + ((s == 2) ? LG_A_LO : LG_A_HI);
            uint32_t baseB = stg + ((s == 1) ? LG_B_LO : LG_B_HI);
            #pragma unroll
            for (int kk = 0; kk < 32; kk += 16) {
                uint32_t a0, a1, a2, a3;
                ldmatrix_x4(a0, a1, a2, a3, baseA + (uint32_t)(a_off + kk) * 2);
                #pragma unroll
                for (int nt = 0; nt < 8; nt++) {
                    uint32_t b0, b1;
                    ldmatrix_x2(b0, b1,
                        baseB + (uint32_t)(b_lane + (warp_n * 64 + nt * 8) * ASTR + kk) * 2);
                    mma_16816(acc[nt], a0, a1, a2, a3, b0, b1);
                }
            }
        }
        __syncthreads();
    }

    // phase 1: bias + residual, stage fp32 rows in smem
    float* fb = (float*)smem;
    #pragma unroll
    for (int nt = 0; nt < 8; nt++) {
        int col = warp_n * 64 + nt * 8 + (lane & 3) * 2;
        int rl  = warp_m * 16 + (lane >> 2);
        #pragma unroll
        for (int half = 0; half < 2; half++) {
            int r = rl + half * 8;
            size_t grb = (size_t)(row0 + r) * DD;
            float v0 = acc[nt][half * 2 + 0];
            float v1 = acc[nt][half * 2 + 1];
            if (BIAS) { v0 += bias[col]; v1 += bias[col + 1]; }
            v0 += resp[grb + col];
            v1 += resp[grb + col + 1];
            fb[r * DD + col] = v0;
            fb[r * DD + col + 1] = v1;
        }
    }
    __syncthreads();

    // phase 2: warp-per-row LayerNorm (each warp: 4 rows)
    float g = gamma[gi], bb = beta[gi];
    #pragma unroll
    for (int j = 0; j < 4; j++) {
        int r = wid * 4 + j;
        const float4* rp = (const float4*)(fb + r * DD);
        float4 v0 = rp[lane * 2], v1 = rp[lane * 2 + 1];

        float sum = v0.x + v0.y + v0.z + v0.w + v1.x + v1.y + v1.z + v1.w;
        #pragma unroll
        for (int off = 16; off > 0; off >>= 1)
            sum += __shfl_xor_sync(0xffffffffu, sum, off);
        float mean = sum * (1.0f / DD);

        float d0 = v0.x - mean, d1 = v0.y - mean, d2 = v0.z - mean, d3 = v0.w - mean;
        float d4 = v1.x - mean, d5 = v1.y - mean, d6 = v1.z - mean, d7 = v1.w - mean;
        float s2 = d0*d0 + d1*d1 + d2*d2 + d3*d3 + d4*d4 + d5*d5 + d6*d6 + d7*d7;
        #pragma unroll
        for (int off = 16; off > 0; off >>= 1)
            s2 += __shfl_xor_sync(0xffffffffu, s2, off);
        float rstd = rsqrtf(s2 * (1.0f / DD) + 1e-14f) * g;

        float o[8] = { d0*rstd + bb, d1*rstd + bb, d2*rstd + bb, d3*rstd + bb,
                       d4*rstd + bb, d5*rstd + bb, d6*rstd + bb, d7*rstd + bb };
        size_t gbase = (size_t)(row0 + r) * DD + lane * 8;
        *(float4*)(xout + gbase)     = make_float4(o[0], o[1], o[2], o[3]);
        *(float4*)(xout + gbase + 4) = make_float4(o[4], o[5], o[6], o[7]);
        if (SPLITOUT) {
            #pragma unroll
            for (int p = 0; p < 4; p++)
                split_store2(o[2*p], o[2*p+1], Xhi, Xlo, gbase + 2*p);
        }
    }
}

// ---------------------------------------------------------------------------
// HMMA flash attention, fp16 splits, cp.async 2-stage KV pipeline.
// 128 queries/CTA, 64-key tiles, 4 warps. q pre-scaled by log2e.
// QK: 3 passes. PV: single pass (V hi only).
// ---------------------------------------------------------------------------
#define ATT_Q_HI 0
#define ATT_Q_LO 10240
#define ATT_KV0  20480            // + stage*15360 + {Khi:0, Klo:5120, Vhi:10240}
#define ATT_KSTG 15360
#define ATT_M0   51200            // + stage*256
#define ATT_SMEM 51712

__global__ void __launch_bounds__(128) attention_hmma(const float* __restrict__ mask) {
    extern __shared__ char smem[];
    uint32_t sb = smem_u32(smem);

    int b = blockIdx.y >> 3, h = blockIdx.y & 7;
    int t = threadIdx.x, warp = t >> 5, lane = t & 31;
    int row0 = blockIdx.x * 128;

    auto load_kv = [&](int s, int t0) {
        uint32_t ub = sb + ATT_KV0 + s * ATT_KSTG;
        #pragma unroll
        for (int l = 0; l < 4; l++) {           // K hi/lo
            int idx = t + l * 128;              // [0,512)
            int r = idx >> 3, which = (idx >> 2) & 1, c4 = idx & 3;
            const __half* src = which ? g_qkvlo : g_qkvhi;
            cp16(ub + which * 5120 + r * 80 + c4 * 16,
                 src + (size_t)(b * SS + t0 + r) * QKV3 + DD + h * DK + c4 * 8);
        }
        #pragma unroll
        for (int l = 0; l < 2; l++) {           // V hi only
            int idx = t + l * 128;              // [0,256)
            int r = idx >> 2, c4 = idx & 3;
            cp16(ub + 10240 + r * 80 + c4 * 16,
                 g_qkvhi + (size_t)(b * SS + t0 + r) * QKV3 + 2 * DD + h * DK + c4 * 8);
        }
        if (t < 64)
            *(float*)(smem + ATT_M0 + s * 256 + t * 4) = mask[b * SS + t0 + t];
    };

    load_kv(0, 0);
    CP_COMMIT();

    // Q (hi/lo) regular loads
    {
        size_t qbase = (size_t)(b * SS + row0) * QKV3 + h * DK;
        #pragma unroll
        for (int l = 0; l < 8; l++) {
            int idx = t + l * 128;
            int r = idx >> 3, which = (idx >> 2) & 1, c4 = idx & 3;
            const __half* src = which ? g_qkvlo : g_qkvhi;
            *(uint4*)(smem + (which ? ATT_Q_LO : ATT_Q_HI) + r * 80 + c4 * 16) =
                *(const uint4*)&src[qbase + (size_t)r * QKV3 + c4 * 8];
        }
    }
    __syncthreads();

    uint32_t qf[2][2][2][4];
    {
        int a_off = (warp * 32 + (lane & 15)) * ASTR + (lane >> 4) * 8;
        #pragma unroll
        for (int w2 = 0; w2 < 2; w2++) {
            uint32_t base = sb + (w2 ? ATT_Q_LO : ATT_Q_HI);
            #pragma unroll
            for (int mt = 0; mt < 2; mt++)
                #pragma unroll
                for (int ks = 0; ks < 2; ks++)
                    ldmatrix_x4(qf[w2][mt][ks][0], qf[w2][mt][ks][1],
                                qf[w2][mt][ks][2], qf[w2][mt][ks][3],
                                base + (uint32_t)(a_off + mt * 16 * ASTR + ks * 16) * 2);
        }
    }

    float m_run[2][2], l_run[2][2], oacc[2][4][4];
    #pragma unroll
    for (int mt = 0; mt < 2; mt++) {
        #pragma unroll
        for (int hf = 0; hf < 2; hf++) { m_run[mt][hf] = -1e30f; l_run[mt][hf] = 0.f; }
        #pragma unroll
        for (int nt = 0; nt < 4; nt++)
            #pragma unroll
            for (int e = 0; e < 4; e++) oacc[mt][nt][e] = 0.f;
    }

    const int ntiles = SS / 64;
    for (int i = 0; i < ntiles; i++) {
        if (i + 1 < ntiles) { load_kv((i + 1) & 1, (i + 1) * 64); CP_COMMIT(); CP_WAIT(1); }
        else                { CP_WAIT(0); }
        __syncthreads();

        uint32_t kvstg = sb + ATT_KV0 + (i & 1) * ATT_KSTG;
        const float* sM = (const float*)(smem + ATT_M0 + (i & 1) * 256);

        float sc[2][8][4];
        #pragma unroll
        for (int mt = 0; mt < 2; mt++)
            #pragma unroll
            for (int nt = 0; nt < 8; nt++)
                #pragma unroll
                for (int e = 0; e < 4; e++) sc[mt][nt][e] = 0.f;
        {
            int b_off = (lane & 7) * ASTR + ((lane >> 3) & 1) * 8;
            #pragma unroll
            for (int s = 0; s < 3; s++) {
                int wa = (s == 2) ? 1 : 0;
                uint32_t kbase = kvstg + ((s == 1) ? 5120 : 0);
                #pragma unroll
                for (int ks = 0; ks < 2; ks++)
                    #pragma unroll
                    for (int nt = 0; nt < 8; nt++) {
                        uint32_t b0, b1;
                        ldmatrix_x2(b0, b1,
                            kbase + (uint32_t)(b_off + nt * 8 * ASTR + ks * 16) * 2);
                        mma_16816(sc[0][nt], qf[wa][0][ks][0], qf[wa][0][ks][1],
                                  qf[wa][0][ks][2], qf[wa][0][ks][3], b0, b1);
                        mma_16816(sc[1][nt], qf[wa][1][ks][0], qf[wa][1][ks][1],
                                  qf[wa][1][ks][2], qf[wa][1][ks][3], b0, b1);
                    }
            }
        }

        float tmax[2][2] = {{-1e30f, -1e30f}, {-1e30f, -1e30f}};
        #pragma unroll
        for (int nt = 0; nt < 8; nt++) {
            int c0 = nt * 8 + (lane & 3) * 2;
            float mvA = sM[c0], mvB = sM[c0 + 1];
            float cA = (1.f - mvA) * MV2L, cB = (1.f - mvB) * MV2L;
            #pragma unroll
            for (int mt = 0; mt < 2; mt++) {
                sc[mt][nt][0] = fmaf(mvA, sc[mt][nt][0], cA);
                sc[mt][nt][1] = fmaf(mvB, sc[mt][nt][1], cB);
                sc[mt][nt][2] = fmaf(mvA, sc[mt][nt][2], cA);
                sc[mt][nt][3] = fmaf(mvB, sc[mt][nt][3], cB);
                tmax[mt][0] = fmaxf(tmax[mt][0], fmaxf(sc[mt][nt][0], sc[mt][nt][1]));
                tmax[mt][1] = fmaxf(tmax[mt][1], fmaxf(sc[mt][nt][2], sc[mt][nt][3]));
            }
        }
        float corr[2][2];
        #pragma unroll
        for (int mt = 0; mt < 2; mt++)
            #pragma unroll
            for (int hf = 0; hf < 2; hf++) {
                float v = tmax[mt][hf];
                v = fmaxf(v, __shfl_xor_sync(0xffffffffu, v, 1));
                v = fmaxf(v, __shfl_xor_sync(0xffffffffu, v, 2));
                float mn = fmaxf(m_run[mt][hf], v);
                corr[mt][hf] = ex2f(m_run[mt][hf] - mn);
                m_run[mt][hf] = mn;
                l_run[mt][hf] *= corr[mt][hf];
            }
        #pragma unroll
        for (int mt = 0; mt < 2; mt++)
            #pragma unroll
            for (int nt = 0; nt < 4; nt++)
                #pragma unroll
                for (int e = 0; e < 4; e++)
                    oacc[mt][nt][e] *= corr[mt][e >> 1];

        uint32_t pf[2][4][4];
        #pragma unroll
        for (int mt = 0; mt < 2; mt++)
            #pragma unroll
            for (int nt = 0; nt < 8; nt++) {
                float p0 = ex2f(sc[mt][nt][0] - m_run[mt][0]);
                float p1 = ex2f(sc[mt][nt][1] - m_run[mt][0]);
                float p2 = ex2f(sc[mt][nt][2] - m_run[mt][1]);
                float p3 = ex2f(sc[mt][nt][3] - m_run[mt][1]);
                l_run[mt][0] += p0 + p1;
                l_run[mt][1] += p2 + p3;
                int kb = nt >> 1, hi2 = (nt & 1) * 2;
                pf[mt][kb][hi2 + 0] = pack_h2(p0, p1);
                pf[mt][kb][hi2 + 1] = pack_h2(p2, p3);
            }

        // O += P @ Vhi (single pass)
        {
            uint32_t vbase = kvstg + 10240;
            #pragma unroll
            for (int kb = 0; kb < 4; kb++) {
                uint32_t vrow = vbase + (uint32_t)((kb * 16 + (lane & 15)) * ASTR) * 2;
                #pragma unroll
                for (int nt = 0; nt < 4; nt++) {
                    uint32_t b0, b1;
                    ldmatrix_x2_trans(b0, b1, vrow + (uint32_t)(nt * 8) * 2);
                    mma_16816(oacc[0][nt], pf[0][kb][0], pf[0][kb][1],
                              pf[0][kb][2], pf[0][kb][3], b0, b1);
                    mma_16816(oacc[1][nt], pf[1][kb][0], pf[1][kb][1],
                              pf[1][kb][2], pf[1][kb][3], b0, b1);
                }
            }
        }
        __syncthreads();
    }

    #pragma unroll
    for (int mt = 0; mt < 2; mt++)
        #pragma unroll
        for (int hf = 0; hf < 2; hf++) {
            float v = l_run[mt][hf];
            v += __shfl_xor_sync(0xffffffffu, v, 1);
            v += __shfl_xor_sync(0xffffffffu, v, 2);
            l_run[mt][hf] = 1.0f / v;
        }
    #pragma unroll
    for (int mt = 0; mt < 2; mt++)
        #pragma unroll
        for (int hf = 0; hf < 2; hf++) {
            int row = row0 + warp * 32 + mt * 16 + (lane >> 2) + hf * 8;
            size_t obase = (size_t)(b * SS + row) * DD + h * DV;
            float inv = l_run[mt][hf];
            #pragma unroll
            for (int nt = 0; nt < 4; nt++) {
                int col = nt * 8 + (lane & 3) * 2;
                split_store2(oacc[mt][nt][hf * 2 + 0] * inv,
                             oacc[mt][nt][hf * 2 + 1] * inv,
                             g_ohi, g_olo, obase + col);
            }
        }
}

// ---------------------------------------------------------------------------
// launch
// ---------------------------------------------------------------------------
extern "C" void kernel_launch(void* const* d_in, const int* in_sizes, int n_in,
                              void* d_out, int out_size) {
    const float* x     = (const float*)d_in[0];
    const float* mask  = (const float*)d_in[1];
    const float* Wq    = (const float*)d_in[2];
    const float* Wk    = (const float*)d_in[3];
    const float* Wv    = (const float*)d_in[4];
    const float* Wo    = (const float*)d_in[5];
    const float* W1    = (const float*)d_in[6];
    const float* b1    = (const float*)d_in[7];
    const float* W2    = (const float*)d_in[8];
    const float* b2    = (const float*)d_in[9];
    const float* gamma = (const float*)d_in[10];
    const float* beta  = (const float*)d_in[11];
    float* out = (float*)d_out;
    (void)in_sizes; (void)n_in; (void)out_size;

    float *p_x;
    __half *p_xhi, *p_xlo, *p_ohi, *p_olo, *p_hhi, *p_hlo, *p_qkvhi, *p_qkvlo;
    __half *p_wqkvhi, *p_wqkvlo, *p_wohi, *p_wolo, *p_w1hi, *p_w1lo, *p_w2hi, *p_w2lo;
    cudaGetSymbolAddress((void**)&p_x, g_x);
    cudaGetSymbolAddress((void**)&p_xhi, g_xhi);
    cudaGetSymbolAddress((void**)&p_xlo, g_xlo);
    cudaGetSymbolAddress((void**)&p_qkvhi, g_qkvhi);
    cudaGetSymbolAddress((void**)&p_qkvlo, g_qkvlo);
    cudaGetSymbolAddress((void**)&p_ohi, g_ohi);
    cudaGetSymbolAddress((void**)&p_olo, g_olo);
    cudaGetSymbolAddress((void**)&p_hhi, g_hhi);
    cudaGetSymbolAddress((void**)&p_hlo, g_hlo);
    cudaGetSymbolAddress((void**)&p_wqkvhi, g_wqkvhi);
    cudaGetSymbolAddress((void**)&p_wqkvlo, g_wqkvlo);
    cudaGetSymbolAddress((void**)&p_wohi, g_wohi);
    cudaGetSymbolAddress((void**)&p_wolo, g_wolo);
    cudaGetSymbolAddress((void**)&p_w1hi, g_w1hi);
    cudaGetSymbolAddress((void**)&p_w1lo, g_w1lo);
    cudaGetSymbolAddress((void**)&p_w2hi, g_w2hi);
    cudaGetSymbolAddress((void**)&p_w2lo, g_w2lo);

    cudaFuncSetAttribute(hmma_gemm<false,false,true>,
                         cudaFuncAttributeMaxDynamicSharedMemorySize, G_SMEM);
    cudaFuncSetAttribute(hmma_gemm<true,true,false>,
                         cudaFuncAttributeMaxDynamicSharedMemorySize, G_SMEM);
    cudaFuncSetAttribute(ln_gemm<false,true>,
                         cudaFuncAttributeMaxDynamicSharedMemorySize, LG_SMEM);
    cudaFuncSetAttribute(ln_gemm<true,true>,
                         cudaFuncAttributeMaxDynamicSharedMemorySize, LG_SMEM);
    cudaFuncSetAttribute(ln_gemm<true,false>,
                         cudaFuncAttributeMaxDynamicSharedMemorySize, LG_SMEM);
    cudaFuncSetAttribute(attention_hmma,
                         cudaFuncAttributeMaxDynamicSharedMemorySize, ATT_SMEM);

    copy_kernel<<<MTOT, DD>>>(x);
    pack_qkv_kernel<<<dim3(QKV3 * DD / 256, NLAYER), 256>>>(Wq, Wk, Wv);
    pack_wt_kernel<<<dim3(DD/32, DD/32, NLAYER), 256>>>(Wo, p_wohi, p_wolo, DD, DD);
    pack_wt_kernel<<<dim3(DD/32, DFF/32, NLAYER), 256>>>(W1, p_w1hi, p_w1lo, DD, DFF);
    pack_wt_kernel<<<dim3(DFF/32, DD/32, NLAYER), 256>>>(W2, p_w2hi, p_w2lo, DFF, DD);

    for (int i = 0; i < NLAYER; i++) {
        // qkv = x @ Wqkv  (split fp16 out; q scaled by log2e)
        hmma_gemm<false,false,true><<<dim3(QKV3/64, MTOT/128), 256, G_SMEM>>>(
            p_xhi, p_xlo,
            p_wqkvhi + (size_t)i * QKV3 * DD, p_wqkvlo + (size_t)i * QKV3 * DD,
            nullptr, p_qkvhi, p_qkvlo, MTOT, QKV3, DD);

        // flash attention -> o split fp16
        attention_hmma<<<dim3(SS/128, BB*HH), 128, ATT_SMEM>>>(mask);

        // x = LN(x + o @ Wo)  (fused)
        ln_gemm<false,true><<<MTOT/32, 256, LG_SMEM>>>(
            p_ohi, p_olo,
            p_wohi + (size_t)i * DD * DD, p_wolo + (size_t)i * DD * DD,
            nullptr, p_x, p_x, p_xhi, p_xlo, gamma, beta, 2*i, DD);

        // h = relu(x @ W1 + b1) -> split fp16
        hmma_gemm<true,true,false><<<dim3(DFF/64, MTOT/128), 256, G_SMEM>>>(
            p_xhi, p_xlo,
            p_w1hi + (size_t)i * DFF * DD, p_w1lo + (size_t)i * DFF * DD,
            b1 + (size_t)i * DFF, p_hhi, p_hlo, MTOT, DFF, DD);

        // x = LN(x + h @ W2 + b2)  (fused; final layer -> out)
        if (i == NLAYER - 1) {
            ln_gemm<true,false><<<MTOT/32, 256, LG_SMEM>>>(
                p_hhi, p_hlo,
                p_w2hi + (size_t)i * DD * DFF, p_w2lo + (size_t)i * DD * DFF,
                b2 + (size_t)i * DD, p_x, out, nullptr, nullptr,
                gamma, beta, 2*i+1, DFF);
        } else {
            ln_gemm<true,true><<<MTOT/32, 256, LG_SMEM>>>(
                p_hhi, p_hlo,
                p_w2hi + (size_t)i * DD * DFF, p_w2lo + (size_t)i * DD * DFF,
                b2 + (size_t)i * DD, p_x, p_x, p_xhi, p_xlo,
                gamma, beta, 2*i+1, DFF);
        }
    }
}

// round 7
// speedup vs baseline: 3.2707x; 1.0038x over previous
#include <cuda_runtime.h>
#include <cuda_fp16.h>
#include <cstdint>
#include <math.h>

// Problem constants
#define BB 2
#define SS 2048
#define DD 256
#define HH 8
#define DK 32
#define DV 32
#define DFF 512
#define NLAYER 2
#define MTOT (BB*SS)          // 4096
#define QKV3 (3*DD)           // 768

#define LOG2E 1.4426950408889634f
#define MV2L (-1e-30f * LOG2E)

// ---------------------------------------------------------------------------
// helpers
// ---------------------------------------------------------------------------
__device__ __forceinline__ uint32_t smem_u32(const void* p) {
    uint32_t a;
    asm("{ .reg .u64 tmp; cvta.to.shared.u64 tmp, %1; cvt.u32.u64 %0, tmp; }"
        : "=r"(a) : "l"(p));
    return a;
}

__device__ __forceinline__ void ldmatrix_x4(uint32_t& a0, uint32_t& a1,
                                            uint32_t& a2, uint32_t& a3,
                                            uint32_t addr) {
    asm volatile("ldmatrix.sync.aligned.m8n8.x4.shared.b16 {%0,%1,%2,%3}, [%4];"
                 : "=r"(a0), "=r"(a1), "=r"(a2), "=r"(a3) : "r"(addr));
}

__device__ __forceinline__ void ldmatrix_x4_trans(uint32_t& a0, uint32_t& a1,
                                                  uint32_t& a2, uint32_t& a3,
                                                  uint32_t addr) {
    asm volatile("ldmatrix.sync.aligned.m8n8.x4.trans.shared.b16 {%0,%1,%2,%3}, [%4];"
                 : "=r"(a0), "=r"(a1), "=r"(a2), "=r"(a3) : "r"(addr));
}

__device__ __forceinline__ void mma_16816(float* c, uint32_t a0, uint32_t a1,
                                          uint32_t a2, uint32_t a3,
                                          uint32_t b0, uint32_t b1) {
    asm volatile(
        "mma.sync.aligned.m16n8k16.row.col.f32.f16.f16.f32 "
        "{%0,%1,%2,%3}, {%4,%5,%6,%7}, {%8,%9}, {%0,%1,%2,%3};"
        : "+f"(c[0]), "+f"(c[1]), "+f"(c[2]), "+f"(c[3])
        : "r"(a0), "r"(a1), "r"(a2), "r"(a3), "r"(b0), "r"(b1));
}

__device__ __forceinline__ float ex2f(float x) {
    float r;
    asm("ex2.approx.f32 %0, %1;" : "=f"(r) : "f"(x));
    return r;
}

__device__ __forceinline__ uint32_t pack_h2(float lo, float hi) {
    __half2 v = __floats2half2_rn(lo, hi);
    return *(uint32_t*)&v;
}

__device__ __forceinline__ void cp16(uint32_t dst, const void* src) {
    asm volatile("cp.async.cg.shared.global [%0], [%1], 16;" :: "r"(dst), "l"(src));
}
#define CP_COMMIT() asm volatile("cp.async.commit_group;" ::: "memory")
#define CP_WAIT(N)  asm volatile("cp.async.wait_group %0;" :: "n"(N) : "memory")

// ---------------------------------------------------------------------------
// Scratch (static device globals; no allocation)
// ---------------------------------------------------------------------------
__device__ float g_x[MTOT*DD];
__device__ __half g_xhi[MTOT*DD], g_xlo[MTOT*DD];
__device__ __half g_qkvhi[MTOT*QKV3], g_qkvlo[MTOT*QKV3];
__device__ __half g_ohi[MTOT*DD], g_olo[MTOT*DD];
__device__ __half g_hhi[MTOT*DFF], g_hlo[MTOT*DFF];
__device__ __half g_wqkvhi[NLAYER*QKV3*DD], g_wqkvlo[NLAYER*QKV3*DD];
__device__ __half g_wohi[NLAYER*DD*DD],   g_wolo[NLAYER*DD*DD];
__device__ __half g_w1hi[NLAYER*DFF*DD],  g_w1lo[NLAYER*DFF*DD];
__device__ __half g_w2hi[NLAYER*DD*DFF],  g_w2lo[NLAYER*DD*DFF];

__device__ __forceinline__ void split_store(float v, __half* hi, __half* lo,
                                            size_t idx) {
    __half h = __float2half_rn(v);
    hi[idx] = h;
    lo[idx] = __float2half_rn(v - __half2float(h));
}

__device__ __forceinline__ void split_store2(float v0, float v1, __half* hi,
                                             __half* lo, size_t idx) {
    __half h0 = __float2half_rn(v0), h1 = __float2half_rn(v1);
    *(__half2*)&hi[idx] = __halves2half2(h0, h1);
    *(__half2*)&lo[idx] = __halves2half2(
        __float2half_rn(v0 - __half2float(h0)),
        __float2half_rn(v1 - __half2float(h1)));
}

// ---------------------------------------------------------------------------
// Unified prep: input copy+split, QKV pack, 3x transpose packs (both layers)
// grid.x = 4096(copy) + 1536(qkv) + 128(Wo) + 256(W1) + 256(W2) = 6272
// ---------------------------------------------------------------------------
__global__ void prep_kernel(const float* __restrict__ x,
                            const float* __restrict__ Wq,
                            const float* __restrict__ Wk,
                            const float* __restrict__ Wv,
                            const float* __restrict__ Wo,
                            const float* __restrict__ W1,
                            const float* __restrict__ W2) {
    __shared__ float tile[32][33];
    int bid = blockIdx.x;
    int t = threadIdx.x;

    if (bid < 4096) {                       // input copy + split
        size_t i = (size_t)bid * 256 + t;
        float v = x[i];
        g_x[i] = v;
        split_store(v, g_xhi, g_xlo, i);
        return;
    }
    bid -= 4096;
    if (bid < NLAYER * 768) {               // QKV pack
        int layer = bid / 768;
        int idx = (bid % 768) * 256 + t;    // n*256 + d
        int n = idx >> 8, d = idx & 255;
        int sel = n >> 8;
        int r = n & 255;
        int h = r >> 5, kk = r & 31;
        const float* W = (sel == 0) ? Wq : (sel == 1) ? Wk : Wv;
        float v = W[(size_t)layer * HH * DD * DK + (h * DD + d) * DK + kk];
        split_store(v, g_wqkvhi, g_wqkvlo, (size_t)layer * QKV3 * DD + idx);
        return;
    }
    bid -= NLAYER * 768;

    const float* W; __half *hi, *lo; int KK, NN, layer, tileid;
    if (bid < 128)        { layer = bid >> 6;  tileid = bid & 63;
                            W = Wo; hi = g_wohi; lo = g_wolo; KK = DD;  NN = DD;  }
    else if (bid < 384)   { bid -= 128; layer = bid >> 7; tileid = bid & 127;
                            W = W1; hi = g_w1hi; lo = g_w1lo; KK = DD;  NN = DFF; }
    else                  { bid -= 384; layer = bid >> 7; tileid = bid & 127;
                            W = W2; hi = g_w2hi; lo = g_w2lo; KK = DFF; NN = DD;  }
    W  += (size_t)layer * KK * NN;
    hi += (size_t)layer * KK * NN;
    lo += (size_t)layer * KK * NN;
    int ktiles = KK >> 5;
    int k0 = (tileid % ktiles) * 32, n0 = (tileid / ktiles) * 32;

    int tx = t & 31, ty = t >> 5;
    #pragma unroll
    for (int l = 0; l < 4; l++) {
        int k = ty + l * 8;
        tile[k][tx] = W[(size_t)(k0 + k) * NN + n0 + tx];
    }
    __syncthreads();
    #pragma unroll
    for (int l = 0; l < 4; l++) {
        int n = ty + l * 8;
        split_store(tile[tx][n], hi, lo, (size_t)(n0 + n) * KK + k0 + tx);
    }
}

// ---------------------------------------------------------------------------
// HMMA fp16-split GEMM (CTA 128x64, BK=32, 8 warps 4x2), cp.async 2-stage.
// ---------------------------------------------------------------------------
#define ASTR 40
#define G_A_HI 0
#define G_A_LO 10240
#define G_B_HI 20480
#define G_B_LO 25600
#define G_STG  30720
#define G_SMEM (2*G_STG)   // 61440

template<bool BIAS, bool RELU, bool SCALEQ>
__global__ void __launch_bounds__(256)
hmma_gemm(const __half* __restrict__ Ahi, const __half* __restrict__ Alo,
          const __half* __restrict__ Bhi, const __half* __restrict__ Blo,
          const float* __restrict__ bias,
          __half* __restrict__ Chi, __half* __restrict__ Clo,
          int M, int N, int K) {
    extern __shared__ char smem[];
    uint32_t sb = smem_u32(smem);

    int t = threadIdx.x, wid = t >> 5, lane = t & 31;
    int warp_m = wid & 3;
    int warp_n = wid >> 2;
    int row0 = blockIdx.y * 128, col0 = blockIdx.x * 64;

    float acc[2][4][4];
    #pragma unroll
    for (int mt = 0; mt < 2; mt++)
        #pragma unroll
        for (int nt = 0; nt < 4; nt++)
            #pragma unroll
            for (int e = 0; e < 4; e++) acc[mt][nt][e] = 0.0f;

    int a_off  = (warp_m * 32 + (lane & 15)) * ASTR + (lane >> 4) * 8;
    int b_off4 = (warp_n * 32 + (lane & 7) + ((lane >> 4) << 3)) * ASTR
               + (((lane >> 3) & 1) << 3);

    auto load_stage = [&](int s, int kc) {
        uint32_t ub = sb + s * G_STG;
        #pragma unroll
        for (int l = 0; l < 2; l++) {
            int idx = t + l * 256;
            int r = idx >> 2, c4 = idx & 3;
            size_t gsrc = (size_t)(row0 + r) * K + kc + c4 * 8;
            cp16(ub + G_A_HI + r * 80 + c4 * 16, Ahi + gsrc);
            cp16(ub + G_A_LO + r * 80 + c4 * 16, Alo + gsrc);
        }
        {
            int r = t >> 2, c4 = t & 3;
            size_t gsrc = (size_t)(col0 + r) * K + kc + c4 * 8;
            cp16(ub + G_B_HI + r * 80 + c4 * 16, Bhi + gsrc);
            cp16(ub + G_B_LO + r * 80 + c4 * 16, Blo + gsrc);
        }
    };

    int nk = K >> 5;
    load_stage(0, 0);
    CP_COMMIT();

    for (int i = 0; i < nk; i++) {
        if (i + 1 < nk) { load_stage((i + 1) & 1, (i + 1) * 32); CP_COMMIT(); CP_WAIT(1); }
        else            { CP_WAIT(0); }
        __syncthreads();

        uint32_t stg = sb + (i & 1) * G_STG;
        #pragma unroll
        for (int s = 0; s < 3; s++) {
            uint32_t baseA = stg + ((s == 2) ? G_A_LO : G_A_HI);
            uint32_t baseB = stg + ((s == 1) ? G_B_LO : G_B_HI);
            #pragma unroll
            for (int kk = 0; kk < 32; kk += 16) {
                uint32_t afr[2][4];
                #pragma unroll
                for (int mt = 0; mt < 2; mt++)
                    ldmatrix_x4(afr[mt][0], afr[mt][1], afr[mt][2], afr[mt][3],
                                baseA + (uint32_t)(a_off + mt * 16 * ASTR + kk) * 2);
                uint32_t bfr[4][2];
                #pragma unroll
                for (int p = 0; p < 2; p++)
                    ldmatrix_x4(bfr[2*p][0], bfr[2*p][1], bfr[2*p+1][0], bfr[2*p+1][1],
                                baseB + (uint32_t)(b_off4 + p * 16 * ASTR + kk) * 2);
                #pragma unroll
                for (int mt = 0; mt < 2; mt++)
                    #pragma unroll
                    for (int nt = 0; nt < 4; nt++)
                        mma_16816(acc[mt][nt], afr[mt][0], afr[mt][1], afr[mt][2],
                                  afr[mt][3], bfr[nt][0], bfr[nt][1]);
            }
        }
        __syncthreads();
    }

    #pragma unroll
    for (int mt = 0; mt < 2; mt++) {
        int r_lo = row0 + warp_m * 32 + mt * 16 + (lane >> 2);
        #pragma unroll
        for (int nt = 0; nt < 4; nt++) {
            int c = col0 + warp_n * 32 + nt * 8 + (lane & 3) * 2;
            #pragma unroll
            for (int half = 0; half < 2; half++) {
                int r = r_lo + half * 8;
                size_t rb = (size_t)r * N;
                float v0 = acc[mt][nt][half * 2 + 0];
                float v1 = acc[mt][nt][half * 2 + 1];
                if (BIAS) { v0 += bias[c]; v1 += bias[c + 1]; }
                if (RELU) { v0 = fmaxf(v0, 0.0f); v1 = fmaxf(v1, 0.0f); }
                if (SCALEQ) { if (c < DD) { v0 *= LOG2E; v1 *= LOG2E; } }
                split_store2(v0, v1, Chi, Clo, rb + c);
            }
        }
    }
}

// ---------------------------------------------------------------------------
// GEMM + residual + LayerNorm fused (Wo and W2 paths). Tile 32x256.
// ---------------------------------------------------------------------------
#define LG_A_HI 0
#define LG_A_LO 2560
#define LG_B_HI 5120
#define LG_B_LO 25600
#define LG_STG  46080
#define LG_SMEM (2*LG_STG)   // 92160

template<bool BIAS, bool SPLITOUT>
__global__ void __launch_bounds__(256)
ln_gemm(const __half* __restrict__ Ahi, const __half* __restrict__ Alo,
        const __half* __restrict__ Bhi, const __half* __restrict__ Blo,
        const float* __restrict__ bias, const float* __restrict__ resp,
        float* __restrict__ xout, __half* __restrict__ Xhi,
        __half* __restrict__ Xlo, const float* __restrict__ gamma,
        const float* __restrict__ beta, int gi, int K) {
    extern __shared__ char smem[];
    uint32_t sb = smem_u32(smem);

    int t = threadIdx.x, wid = t >> 5, lane = t & 31;
    int warp_m = wid & 1;
    int warp_n = wid >> 1;
    int row0 = blockIdx.x * 32;

    float acc[8][4];
    #pragma unroll
    for (int nt = 0; nt < 8; nt++)
        #pragma unroll
        for (int e = 0; e < 4; e++) acc[nt][e] = 0.0f;

    int a_off   = (warp_m * 16 + (lane & 15)) * ASTR + (lane >> 4) * 8;
    int b_lane4 = ((lane & 7) + ((lane >> 4) << 3)) * ASTR + (((lane >> 3) & 1) << 3);

    auto load_stage = [&](int s, int kc) {
        uint32_t ub = sb + s * LG_STG;
        {
            int idx = t;
            int r = idx >> 3, which = (idx >> 2) & 1, c4 = idx & 3;
            size_t gsrc = (size_t)(row0 + r) * K + kc + c4 * 8;
            cp16(ub + (which ? LG_A_LO : LG_A_HI) + r * 80 + c4 * 16,
                 (which ? Alo : Ahi) + gsrc);
        }
        #pragma unroll
        for (int l = 0; l < 8; l++) {
            int idx = t + l * 256;
            int r = idx >> 3, which = (idx >> 2) & 1, c4 = idx & 3;
            size_t gsrc = (size_t)r * K + kc + c4 * 8;
            cp16(ub + (which ? LG_B_LO : LG_B_HI) + r * 80 + c4 * 16,
                 (which ? Blo : Bhi) + gsrc);
        }
    };

    int nk = K >> 5;
    load_stage(0, 0);
    CP_COMMIT();

    for (int i = 0; i < nk; i++) {
        if (i + 1 < nk) { load_stage((i + 1) & 1, (i + 1) * 32); CP_COMMIT(); CP_WAIT(1); }
        else            { CP_WAIT(0); }
        __syncthreads();

        uint32_t stg = sb + (i & 1) * LG_STG;
        #pragma unroll
        for (int s = 0; s < 3; s++) {
            uint32_t baseA = stg + ((s == 2) ? LG_A_LO : LG_A_HI);
            uint32_t baseB = stg + ((s == 1) ? LG_B_LO : LG_B_HI);
            #pragma unroll
            for (int kk = 0; kk < 32; kk += 16) {
                uint32_t a0, a1, a2, a3;
                ldmatrix_x4(a0, a1, a2, a3, baseA + (uint32_t)(a_off + kk) * 2);
                #pragma unroll
                for (int p = 0; p < 4; p++) {
                    uint32_t b0, b1, b2, b3;
                    ldmatrix_x4(b0, b1, b2, b3,
                        baseB + (uint32_t)(b_lane4 + (warp_n * 64 + p * 16) * ASTR + kk) * 2);
                    mma_16816(acc[2*p],   a0, a1, a2, a3, b0, b1);
                    mma_16816(acc[2*p+1], a0, a1, a2, a3, b2, b3);
                }
            }
        }
        __syncthreads();
    }

    // phase 1: bias + residual into fp32 smem rows
    float* fb = (float*)smem;
    #pragma unroll
    for (int nt = 0; nt < 8; nt++) {
        int col = warp_n * 64 + nt * 8 + (lane & 3) * 2;
        int rl  = warp_m * 16 + (lane >> 2);
        #pragma unroll
        for (int half = 0; half < 2; half++) {
            int r = rl + half * 8;
            size_t grb = (size_t)(row0 + r) * DD;
            float v0 = acc[nt][half * 2 + 0];
            float v1 = acc[nt][half * 2 + 1];
            if (BIAS) { v0 += bias[col]; v1 += bias[col + 1]; }
            v0 += resp[grb + col];
            v1 += resp[grb + col + 1];
            fb[r * DD + col] = v0;
            fb[r * DD + col + 1] = v1;
        }
    }
    __syncthreads();

    // phase 2: warp-per-row LayerNorm
    float g = gamma[gi], bb = beta[gi];
    #pragma unroll
    for (int j = 0; j < 4; j++) {
        int r = wid * 4 + j;
        const float4* rp = (const float4*)(fb + r * DD);
        float4 v0 = rp[lane * 2], v1 = rp[lane * 2 + 1];

        float sum = v0.x + v0.y + v0.z + v0.w + v1.x + v1.y + v1.z + v1.w;
        #pragma unroll
        for (int off = 16; off > 0; off >>= 1)
            sum += __shfl_xor_sync(0xffffffffu, sum, off);
        float mean = sum * (1.0f / DD);

        float d0 = v0.x - mean, d1 = v0.y - mean, d2 = v0.z - mean, d3 = v0.w - mean;
        float d4 = v1.x - mean, d5 = v1.y - mean, d6 = v1.z - mean, d7 = v1.w - mean;
        float s2 = d0*d0 + d1*d1 + d2*d2 + d3*d3 + d4*d4 + d5*d5 + d6*d6 + d7*d7;
        #pragma unroll
        for (int off = 16; off > 0; off >>= 1)
            s2 += __shfl_xor_sync(0xffffffffu, s2, off);
        float rstd = rsqrtf(s2 * (1.0f / DD) + 1e-14f) * g;

        float o[8] = { d0*rstd + bb, d1*rstd + bb, d2*rstd + bb, d3*rstd + bb,
                       d4*rstd + bb, d5*rstd + bb, d6*rstd + bb, d7*rstd + bb };
        size_t gbase = (size_t)(row0 + r) * DD + lane * 8;
        *(float4*)(xout + gbase)     = make_float4(o[0], o[1], o[2], o[3]);
        *(float4*)(xout + gbase + 4) = make_float4(o[4], o[5], o[6], o[7]);
        if (SPLITOUT) {
            #pragma unroll
            for (int p = 0; p < 4; p++)
                split_store2(o[2*p], o[2*p+1], Xhi, Xlo, gbase + 2*p);
        }
    }
}

// ---------------------------------------------------------------------------
// HMMA flash attention: fp16 splits, cp.async 2-stage KV.
// QK: 3 passes. PV: 2 passes (Vhi + Vlo). ldsm.x4 everywhere.
// ---------------------------------------------------------------------------
#define ATT_Q_HI 0
#define ATT_Q_LO 10240
#define ATT_KV0  20480            // + stage*20480 + {Khi:0,Klo:5120,Vhi:10240,Vlo:15360}
#define ATT_KSTG 20480
#define ATT_M0   61440            // + stage*256
#define ATT_SMEM 61952

__global__ void __launch_bounds__(128) attention_hmma(const float* __restrict__ mask) {
    extern __shared__ char smem[];
    uint32_t sb = smem_u32(smem);

    int b = blockIdx.y >> 3, h = blockIdx.y & 7;
    int t = threadIdx.x, warp = t >> 5, lane = t & 31;
    int row0 = blockIdx.x * 128;

    auto load_kv = [&](int s, int t0) {
        uint32_t ub = sb + ATT_KV0 + s * ATT_KSTG;
        #pragma unroll
        for (int l = 0; l < 8; l++) {
            int idx = t + l * 128;
            int r = idx >> 4, which = (idx >> 2) & 3, c4 = idx & 3;
            const __half* src = (which & 1) ? g_qkvlo : g_qkvhi;
            int coff = ((which < 2) ? DD : 2 * DD) + h * DK + c4 * 8;
            cp16(ub + which * 5120 + r * 80 + c4 * 16,
                 src + (size_t)(b * SS + t0 + r) * QKV3 + coff);
        }
        if (t < 64)
            *(float*)(smem + ATT_M0 + s * 256 + t * 4) = mask[b * SS + t0 + t];
    };

    load_kv(0, 0);
    CP_COMMIT();

    {
        size_t qbase = (size_t)(b * SS + row0) * QKV3 + h * DK;
        #pragma unroll
        for (int l = 0; l < 8; l++) {
            int idx = t + l * 128;
            int r = idx >> 3, which = (idx >> 2) & 1, c4 = idx & 3;
            const __half* src = which ? g_qkvlo : g_qkvhi;
            *(uint4*)(smem + (which ? ATT_Q_LO : ATT_Q_HI) + r * 80 + c4 * 16) =
                *(const uint4*)&src[qbase + (size_t)r * QKV3 + c4 * 8];
        }
    }
    __syncthreads();

    uint32_t qf[2][2][2][4];
    {
        int a_off = (warp * 32 + (lane & 15)) * ASTR + (lane >> 4) * 8;
        #pragma unroll
        for (int w2 = 0; w2 < 2; w2++) {
            uint32_t base = sb + (w2 ? ATT_Q_LO : ATT_Q_HI);
            #pragma unroll
            for (int mt = 0; mt < 2; mt++)
                #pragma unroll
                for (int ks = 0; ks < 2; ks++)
                    ldmatrix_x4(qf[w2][mt][ks][0], qf[w2][mt][ks][1],
                                qf[w2][mt][ks][2], qf[w2][mt][ks][3],
                                base + (uint32_t)(a_off + mt * 16 * ASTR + ks * 16) * 2);
        }
    }

    float m_run[2][2], l_run[2][2], oacc[2][4][4];
    #pragma unroll
    for (int mt = 0; mt < 2; mt++) {
        #pragma unroll
        for (int hf = 0; hf < 2; hf++) { m_run[mt][hf] = -1e30f; l_run[mt][hf] = 0.f; }
        #pragma unroll
        for (int nt = 0; nt < 4; nt++)
            #pragma unroll
            for (int e = 0; e < 4; e++) oacc[mt][nt][e] = 0.f;
    }

    const int ntiles = SS / 64;
    for (int i = 0; i < ntiles; i++) {
        if (i + 1 < ntiles) { load_kv((i + 1) & 1, (i + 1) * 64); CP_COMMIT(); CP_WAIT(1); }
        else                { CP_WAIT(0); }
        __syncthreads();

        uint32_t kvstg = sb + ATT_KV0 + (i & 1) * ATT_KSTG;
        const float* sM = (const float*)(smem + ATT_M0 + (i & 1) * 256);

        float sc[2][8][4];
        #pragma unroll
        for (int mt = 0; mt < 2; mt++)
            #pragma unroll
            for (int nt = 0; nt < 8; nt++)
                #pragma unroll
                for (int e = 0; e < 4; e++) sc[mt][nt][e] = 0.f;
        {
            int b_off4 = ((lane & 7) + ((lane >> 4) << 3)) * ASTR
                       + (((lane >> 3) & 1) << 3);
            #pragma unroll
            for (int s = 0; s < 3; s++) {
                int wa = (s == 2) ? 1 : 0;
                uint32_t kbase = kvstg + ((s == 1) ? 5120 : 0);
                #pragma unroll
                for (int ks = 0; ks < 2; ks++)
                    #pragma unroll
                    for (int p = 0; p < 4; p++) {
                        uint32_t b0, b1, b2, b3;
                        ldmatrix_x4(b0, b1, b2, b3,
                            kbase + (uint32_t)(b_off4 + p * 16 * ASTR + ks * 16) * 2);
                        mma_16816(sc[0][2*p],   qf[wa][0][ks][0], qf[wa][0][ks][1],
                                  qf[wa][0][ks][2], qf[wa][0][ks][3], b0, b1);
                        mma_16816(sc[0][2*p+1], qf[wa][0][ks][0], qf[wa][0][ks][1],
                                  qf[wa][0][ks][2], qf[wa][0][ks][3], b2, b3);
                        mma_16816(sc[1][2*p],   qf[wa][1][ks][0], qf[wa][1][ks][1],
                                  qf[wa][1][ks][2], qf[wa][1][ks][3], b0, b1);
                        mma_16816(sc[1][2*p+1], qf[wa][1][ks][0], qf[wa][1][ks][1],
                                  qf[wa][1][ks][2], qf[wa][1][ks][3], b2, b3);
                    }
            }
        }

        float tmax[2][2] = {{-1e30f, -1e30f}, {-1e30f, -1e30f}};
        #pragma unroll
        for (int nt = 0; nt < 8; nt++) {
            int c0 = nt * 8 + (lane & 3) * 2;
            float mvA = sM[c0], mvB = sM[c0 + 1];
            float cA = (1.f - mvA) * MV2L, cB = (1.f - mvB) * MV2L;
            #pragma unroll
            for (int mt = 0; mt < 2; mt++) {
                sc[mt][nt][0] = fmaf(mvA, sc[mt][nt][0], cA);
                sc[mt][nt][1] = fmaf(mvB, sc[mt][nt][1], cB);
                sc[mt][nt][2] = fmaf(mvA, sc[mt][nt][2], cA);
                sc[mt][nt][3] = fmaf(mvB, sc[mt][nt][3], cB);
                tmax[mt][0] = fmaxf(tmax[mt][0], fmaxf(sc[mt][nt][0], sc[mt][nt][1]));
                tmax[mt][1] = fmaxf(tmax[mt][1], fmaxf(sc[mt][nt][2], sc[mt][nt][3]));
            }
        }
        float corr[2][2];
        #pragma unroll
        for (int mt = 0; mt < 2; mt++)
            #pragma unroll
            for (int hf = 0; hf < 2; hf++) {
                float v = tmax[mt][hf];
                v = fmaxf(v, __shfl_xor_sync(0xffffffffu, v, 1));
                v = fmaxf(v, __shfl_xor_sync(0xffffffffu, v, 2));
                float mn = fmaxf(m_run[mt][hf], v);
                corr[mt][hf] = ex2f(m_run[mt][hf] - mn);
                m_run[mt][hf] = mn;
                l_run[mt][hf] *= corr[mt][hf];
            }
        #pragma unroll
        for (int mt = 0; mt < 2; mt++)
            #pragma unroll
            for (int nt = 0; nt < 4; nt++)
                #pragma unroll
                for (int e = 0; e < 4; e++)
                    oacc[mt][nt][e] *= corr[mt][e >> 1];

        uint32_t pf[2][4][4];
        #pragma unroll
        for (int mt = 0; mt < 2; mt++)
            #pragma unroll
            for (int nt = 0; nt < 8; nt++) {
                float p0 = ex2f(sc[mt][nt][0] - m_run[mt][0]);
                float p1 = ex2f(sc[mt][nt][1] - m_run[mt][0]);
                float p2 = ex2f(sc[mt][nt][2] - m_run[mt][1]);
                float p3 = ex2f(sc[mt][nt][3] - m_run[mt][1]);
                l_run[mt][0] += p0 + p1;
                l_run[mt][1] += p2 + p3;
                int kb = nt >> 1, hi2 = (nt & 1) * 2;
                pf[mt][kb][hi2 + 0] = pack_h2(p0, p1);
                pf[mt][kb][hi2 + 1] = pack_h2(p2, p3);
            }

        // O += P @ V (Vhi pass + Vlo pass), trans x4 loads
        #pragma unroll
        for (int s = 0; s < 2; s++) {
            uint32_t vbase = kvstg + (2 + s) * 5120;
            #pragma unroll
            for (int kb = 0; kb < 4; kb++) {
                uint32_t vrow = vbase +
                    (uint32_t)((kb * 16 + (lane & 15)) * ASTR + ((lane >> 4) << 3)) * 2;
                #pragma unroll
                for (int p = 0; p < 2; p++) {
                    uint32_t b0, b1, b2, b3;
                    ldmatrix_x4_trans(b0, b1, b2, b3, vrow + (uint32_t)(p * 16) * 2);
                    mma_16816(oacc[0][2*p],   pf[0][kb][0], pf[0][kb][1],
                              pf[0][kb][2], pf[0][kb][3], b0, b1);
                    mma_16816(oacc[0][2*p+1], pf[0][kb][0], pf[0][kb][1],
                              pf[0][kb][2], pf[0][kb][3], b2, b3);
                    mma_16816(oacc[1][2*p],   pf[1][kb][0], pf[1][kb][1],
                              pf[1][kb][2], pf[1][kb][3], b0, b1);
                    mma_16816(oacc[1][2*p+1], pf[1][kb][0], pf[1][kb][1],
                              pf[1][kb][2], pf[1][kb][3], b2, b3);
                }
            }
        }
        __syncthreads();
    }

    #pragma unroll
    for (int mt = 0; mt < 2; mt++)
        #pragma unroll
        for (int hf = 0; hf < 2; hf++) {
            float v = l_run[mt][hf];
            v += __shfl_xor_sync(0xffffffffu, v, 1);
            v += __shfl_xor_sync(0xffffffffu, v, 2);
            l_run[mt][hf] = 1.0f / v;
        }
    #pragma unroll
    for (int mt = 0; mt < 2; mt++)
        #pragma unroll
        for (int hf = 0; hf < 2; hf++) {
            int row = row0 + warp * 32 + mt * 16 + (lane >> 2) + hf * 8;
            size_t obase = (size_t)(b * SS + row) * DD + h * DV;
            float inv = l_run[mt][hf];
            #pragma unroll
            for (int nt = 0; nt < 4; nt++) {
                int col = nt * 8 + (lane & 3) * 2;
                split_store2(oacc[mt][nt][hf * 2 + 0] * inv,
                             oacc[mt][nt][hf * 2 + 1] * inv,
                             g_ohi, g_olo, obase + col);
            }
        }
}

// ---------------------------------------------------------------------------
// launch
// ---------------------------------------------------------------------------
extern "C" void kernel_launch(void* const* d_in, const int* in_sizes, int n_in,
                              void* d_out, int out_size) {
    const float* x     = (const float*)d_in[0];
    const float* mask  = (const float*)d_in[1];
    const float* Wq    = (const float*)d_in[2];
    const float* Wk    = (const float*)d_in[3];
    const float* Wv    = (const float*)d_in[4];
    const float* Wo    = (const float*)d_in[5];
    const float* W1    = (const float*)d_in[6];
    const float* b1    = (const float*)d_in[7];
    const float* W2    = (const float*)d_in[8];
    const float* b2    = (const float*)d_in[9];
    const float* gamma = (const float*)d_in[10];
    const float* beta  = (const float*)d_in[11];
    float* out = (float*)d_out;
    (void)in_sizes; (void)n_in; (void)out_size;

    float *p_x;
    __half *p_xhi, *p_xlo, *p_ohi, *p_olo, *p_hhi, *p_hlo, *p_qkvhi, *p_qkvlo;
    __half *p_wqkvhi, *p_wqkvlo, *p_wohi, *p_wolo, *p_w1hi, *p_w1lo, *p_w2hi, *p_w2lo;
    cudaGetSymbolAddress((void**)&p_x, g_x);
    cudaGetSymbolAddress((void**)&p_xhi, g_xhi);
    cudaGetSymbolAddress((void**)&p_xlo, g_xlo);
    cudaGetSymbolAddress((void**)&p_qkvhi, g_qkvhi);
    cudaGetSymbolAddress((void**)&p_qkvlo, g_qkvlo);
    cudaGetSymbolAddress((void**)&p_ohi, g_ohi);
    cudaGetSymbolAddress((void**)&p_olo, g_olo);
    cudaGetSymbolAddress((void**)&p_hhi, g_hhi);
    cudaGetSymbolAddress((void**)&p_hlo, g_hlo);
    cudaGetSymbolAddress((void**)&p_wqkvhi, g_wqkvhi);
    cudaGetSymbolAddress((void**)&p_wqkvlo, g_wqkvlo);
    cudaGetSymbolAddress((void**)&p_wohi, g_wohi);
    cudaGetSymbolAddress((void**)&p_wolo, g_wolo);
    cudaGetSymbolAddress((void**)&p_w1hi, g_w1hi);
    cudaGetSymbolAddress((void**)&p_w1lo, g_w1lo);
    cudaGetSymbolAddress((void**)&p_w2hi, g_w2hi);
    cudaGetSymbolAddress((void**)&p_w2lo, g_w2lo);

    cudaFuncSetAttribute(hmma_gemm<false,false,true>,
                         cudaFuncAttributeMaxDynamicSharedMemorySize, G_SMEM);
    cudaFuncSetAttribute(hmma_gemm<true,true,false>,
                         cudaFuncAttributeMaxDynamicSharedMemorySize, G_SMEM);
    cudaFuncSetAttribute(ln_gemm<false,true>,
                         cudaFuncAttributeMaxDynamicSharedMemorySize, LG_SMEM);
    cudaFuncSetAttribute(ln_gemm<true,true>,
                         cudaFuncAttributeMaxDynamicSharedMemorySize, LG_SMEM);
    cudaFuncSetAttribute(ln_gemm<true,false>,
                         cudaFuncAttributeMaxDynamicSharedMemorySize, LG_SMEM);
    cudaFuncSetAttribute(attention_hmma,
                         cudaFuncAttributeMaxDynamicSharedMemorySize, ATT_SMEM);

    // one prep launch: copy + split + all weight packs
    prep_kernel<<<4096 + NLAYER*768 + 128 + 256 + 256, 256>>>(
        x, Wq, Wk, Wv, Wo, W1, W2);

    for (int i = 0; i < NLAYER; i++) {
        // qkv = x @ Wqkv  (split fp16 out; q scaled by log2e)
        hmma_gemm<false,false,true><<<dim3(QKV3/64, MTOT/128), 256, G_SMEM>>>(
            p_xhi, p_xlo,
            p_wqkvhi + (size_t)i * QKV3 * DD, p_wqkvlo + (size_t)i * QKV3 * DD,
            nullptr, p_qkvhi, p_qkvlo, MTOT, QKV3, DD);

        // flash attention -> o split fp16
        attention_hmma<<<dim3(SS/128, BB*HH), 128, ATT_SMEM>>>(mask);

        // x = LN(x + o @ Wo)
        ln_gemm<false,true><<<MTOT/32, 256, LG_SMEM>>>(
            p_ohi, p_olo,
            p_wohi + (size_t)i * DD * DD, p_wolo + (size_t)i * DD * DD,
            nullptr, p_x, p_x, p_xhi, p_xlo, gamma, beta, 2*i, DD);

        // h = relu(x @ W1 + b1) -> split fp16
        hmma_gemm<true,true,false><<<dim3(DFF/64, MTOT/128), 256, G_SMEM>>>(
            p_xhi, p_xlo,
            p_w1hi + (size_t)i * DFF * DD, p_w1lo + (size_t)i * DFF * DD,
            b1 + (size_t)i * DFF, p_hhi, p_hlo, MTOT, DFF, DD);

        // x = LN(x + h @ W2 + b2)  (final layer -> out)
        if (i == NLAYER - 1) {
            ln_gemm<true,false><<<MTOT/32, 256, LG_SMEM>>>(
                p_hhi, p_hlo,
                p_w2hi + (size_t)i * DD * DFF, p_w2lo + (size_t)i * DD * DFF,
                b2 + (size_t)i * DD, p_x, out, nullptr, nullptr,
                gamma, beta, 2*i+1, DFF);
        } else {
            ln_gemm<true,true><<<MTOT/32, 256, LG_SMEM>>>(
                p_hhi, p_hlo,
                p_w2hi + (size_t)i * DD * DFF, p_w2lo + (size_t)i * DD * DFF,
                b2 + (size_t)i * DD, p_x, p_x, p_xhi, p_xlo,
                gamma, beta, 2*i+1, DFF);
        }
    }
}